// round 7
// baseline (speedup 1.0000x reference)
#include <cuda_runtime.h>
#include <cuda_fp16.h>
#include <cstdint>

// ---------------- problem constants ----------------
#define TSZ   512
#define NTILE 64
#define ITN   8

#define GMIN   1e-6f
#define GDIFF  ((float)(1.0e-4 - 1.0e-6))
#define STEPQ  ((float)((1.0e-4 - 1.0e-6) / 15.0))
#define FINF   3.402823466e38f
#define GSCALE 8192.0f
#define GINV   (1.0f / 8192.0f)

typedef unsigned int uint32;
typedef unsigned long long ull;

// ---------------- scratch (static device memory) ----------------
__device__ __half g_xh16[(size_t)1024 * 4096];
__device__ __half g_xl16[(size_t)1024 * 4096];
__device__ __half g_Gh[(size_t)NTILE * TSZ * TSZ];   // geff*8192 hi, [t][n][k]
__device__ __half g_Gl[(size_t)NTILE * TSZ * TSZ];   // geff*8192 lo
__device__ __half g_Qi[(size_t)NTILE * TSZ * TSZ];   // quant code 0..15
__device__ float g_cur [(size_t)NTILE * 1024 * TSZ];  // 128 MB
__device__ float g_part[(size_t)NTILE * 4 * 1024 * 6];
__device__ float g_s[NTILE], g_wmin[NTILE];
__device__ float g_pmin[NTILE * 8], g_pmax[NTILE * 8];
__device__ float g_xsum[1024 * ITN];
__device__ float g_qsum[NTILE * TSZ];                 // per (t,k) colsum of q (exact int)
__device__ float g_idot[(size_t)1024 * ITN * 8];      // x . qsum per (b,it,ot)

// ---------------- PTX helpers ----------------
__device__ __forceinline__ uint32 smem_u32(const void* p) {
    uint32 a;
    asm("{ .reg .u64 t; cvta.to.shared.u64 t, %1; cvt.u32.u64 %0, t; }" : "=r"(a) : "l"(p));
    return a;
}
__device__ __forceinline__ void cpa16(uint32 dst, const void* src) {
    asm volatile("cp.async.cg.shared.global [%0], [%1], 16;" :: "r"(dst), "l"(src));
}
__device__ __forceinline__ void ldm_x4(uint32* r, uint32 addr) {
    asm volatile("ldmatrix.sync.aligned.m8n8.x4.shared.b16 {%0,%1,%2,%3}, [%4];"
                 : "=r"(r[0]), "=r"(r[1]), "=r"(r[2]), "=r"(r[3]) : "r"(addr));
}
__device__ __forceinline__ void mma16816(float* c, const uint32* a, const uint32* b) {
    asm volatile(
        "mma.sync.aligned.m16n8k16.row.col.f32.f16.f16.f32 "
        "{%0,%1,%2,%3}, {%4,%5,%6,%7}, {%8,%9}, {%0,%1,%2,%3};"
        : "+f"(c[0]), "+f"(c[1]), "+f"(c[2]), "+f"(c[3])
        : "r"(a[0]), "r"(a[1]), "r"(a[2]), "r"(a[3]), "r"(b[0]), "r"(b[1]));
}

// ---------------- kernel 1a: per-tile min/max partials ----------------
__global__ void k_minmax_part(const float* __restrict__ w) {
    int t = blockIdx.y, chunk = blockIdx.x;
    int it = t >> 3, ot = t & 7;
    int tid = threadIdx.x;
    float mn = FINF, mx = -FINF;
    int base = chunk * 32768 + tid;
    #pragma unroll 4
    for (int k = 0; k < 128; k++) {
        int e = base + k * 256;
        int i = e >> 9, j = e & 511;
        float v = w[(size_t)(it * TSZ + i) * 4096 + ot * TSZ + j];
        mn = fminf(mn, v); mx = fmaxf(mx, v);
    }
    __shared__ float smn[256], smx[256];
    smn[tid] = mn; smx[tid] = mx;
    __syncthreads();
    for (int o = 128; o > 0; o >>= 1) {
        if (tid < o) {
            smn[tid] = fminf(smn[tid], smn[tid + o]);
            smx[tid] = fmaxf(smx[tid], smx[tid + o]);
        }
        __syncthreads();
    }
    if (tid == 0) { g_pmin[t * 8 + chunk] = smn[0]; g_pmax[t * 8 + chunk] = smx[0]; }
}

__global__ void k_minmax_fin() {
    int t = threadIdx.x;
    if (t < NTILE) {
        float mn = g_pmin[t * 8], mx = g_pmax[t * 8];
        #pragma unroll
        for (int c = 1; c < 8; c++) {
            mn = fminf(mn, g_pmin[t * 8 + c]);
            mx = fmaxf(mx, g_pmax[t * 8 + c]);
        }
        float denom = __fadd_rn(__fsub_rn(mx, mn), 1e-12f);
        g_s[t] = __fdiv_rn(GDIFF, denom);
        g_wmin[t] = mn;
    }
}

// ---------------- kernel 1c: zero qsum (graph-replay safe) ----------------
__global__ void k_zero() {
    g_qsum[blockIdx.x * 1024 + threadIdx.x] = 0.0f;
}

// ---------------- kernel 2: build Gh/Gl/Qi (fp16), [t][n][k]; accumulate colsum(q) ----------------
__global__ void __launch_bounds__(256) k_build(const float* __restrict__ w) {
    __shared__ __half sGh[64][72], sGl[64][72], sQi[64][72];
    int sub = blockIdx.x, t = blockIdx.y;
    int it = t >> 3, ot = t & 7;
    int ib = sub >> 3, jb = sub & 7;
    int i0 = ib * 64, j0 = jb * 64;
    int tid = threadIdx.x;
    float s = g_s[t], wmin = g_wmin[t];

    #pragma unroll
    for (int iter = 0; iter < 16; iter++) {
        int e = iter * 256 + tid;
        int i = e >> 6, j = e & 63;       // i: k, j: n
        float v = w[(size_t)(it * TSZ + i0 + i) * 4096 + ot * TSZ + j0 + j];
        // bit-exact reference op sequence:
        float t1   = __fsub_rn(v, wmin);
        float t2   = __fmul_rn(t1, s);
        float cond = __fadd_rn(t2, GMIN);
        float u    = __fsub_rn(cond, GMIN);
        float vv   = __fdiv_rn(u, STEPQ);
        float q    = rintf(vv);                       // 0..15, exact in fp16
        float cq   = __fadd_rn(__fmul_rn(q, STEPQ), GMIN);
        float inv  = __fdiv_rn(1.0f, cq);
        float rw   = (float)(2 * (513 + (j0 + j) - (i0 + i)));
        float ge   = __fdiv_rn(1.0f, __fadd_rn(inv, rw));
        float gs   = ge * GSCALE;                     // exact pow2 scale
        __half gh  = __float2half_rn(gs);
        __half gl  = __float2half_rn(__fsub_rn(gs, __half2float(gh)));
        sGh[j][i] = gh; sGl[j][i] = gl; sQi[j][i] = __float2half_rn(q);
    }
    __syncthreads();

    size_t obase = (size_t)t * 262144 + (size_t)j0 * 512 + i0;
    #pragma unroll
    for (int iter = 0; iter < 2; iter++) {
        int L = iter * 256 + tid;
        int n = L >> 3, k8 = (L & 7) * 8;
        size_t o = obase + (size_t)n * 512 + k8;
        *(uint4*)&g_Gh[o] = *(const uint4*)&sGh[n][k8];
        *(uint4*)&g_Gl[o] = *(const uint4*)&sGl[n][k8];
        *(uint4*)&g_Qi[o] = *(const uint4*)&sQi[n][k8];
    }

    // column sums of q over this block's 64 j's (exact small integers)
    if (tid < 64) {
        float sum = 0.0f;
        #pragma unroll
        for (int j = 0; j < 64; j++) sum += __half2float(sQi[j][tid]);
        atomicAdd(&g_qsum[t * 512 + i0 + tid], sum);
    }
}

// ---------------- kernel 2b: x -> fp16 hi/lo + per-(b,it) row sums, fused ----------------
__global__ void k_xprep(const float* __restrict__ x) {
    int blk = blockIdx.x;
    int b = blk >> 3, it = blk & 7;
    int tid = threadIdx.x;
    size_t base = (size_t)b * 4096 + it * TSZ + tid * 4;
    float4 v = *(const float4*)&x[base];
    float vs[4] = { v.x, v.y, v.z, v.w };
    __half h[4], l[4];
    #pragma unroll
    for (int i = 0; i < 4; i++) {
        h[i] = __float2half_rn(vs[i]);
        l[i] = __float2half_rn(__fsub_rn(vs[i], __half2float(h[i])));
    }
    *(ull*)&g_xh16[base] = *(const ull*)h;
    *(ull*)&g_xl16[base] = *(const ull*)l;
    float s = vs[0] + vs[1] + vs[2] + vs[3];
    #pragma unroll
    for (int o = 16; o > 0; o >>= 1) s += __shfl_down_sync(0xffffffffu, s, o);
    __shared__ float sm[4];
    if ((tid & 31) == 0) sm[tid >> 5] = s;
    __syncthreads();
    if (tid == 0) g_xsum[b * ITN + it] = sm[0] + sm[1] + sm[2] + sm[3];
}

// ---------------- kernel 3: exact ideal means: idot[b][it][ot] = x_row . qsum ----------------
__global__ void __launch_bounds__(128) k_imean(const float* __restrict__ x) {
    int it = blockIdx.x, b = blockIdx.y, tid = threadIdx.x;
    float4 xv = *(const float4*)&x[(size_t)b * 4096 + it * TSZ + tid * 4];
    float acc[8];
    #pragma unroll
    for (int ot = 0; ot < 8; ot++) {
        const float4 qv = *(const float4*)&g_qsum[(it * 8 + ot) * 512 + tid * 4];
        acc[ot] = xv.x * qv.x + xv.y * qv.y + xv.z * qv.z + xv.w * qv.w;
    }
    __shared__ float sm[4][8];
    #pragma unroll
    for (int ot = 0; ot < 8; ot++) {
        float s = acc[ot];
        #pragma unroll
        for (int o = 16; o > 0; o >>= 1) s += __shfl_down_sync(0xffffffffu, s, o);
        if ((tid & 31) == 0) sm[tid >> 5][ot] = s;
    }
    __syncthreads();
    if (tid < 8)
        g_idot[((size_t)b * ITN + it) * 8 + tid] =
            sm[0][tid] + sm[1][tid] + sm[2][tid] + sm[3][tid];
}

// ---------------- kernel 4: mma.sync GEMM, 4 passes, k-chunk 64, 2-stage ----------------
// passes: cur += xh@Gh + xh@Gl + xl@Gh ; idl += xh@Qi
#define PITCH 144
#define ASZ   18432
#define OFF_XH 0
#define OFF_XL (1 * ASZ)
#define OFF_GH (2 * ASZ)
#define OFF_GL (3 * ASZ)
#define OFF_QI (4 * ASZ)
#define STAGE  (5 * ASZ)
#define SMEM_GEMM (2 * STAGE)

__global__ void __launch_bounds__(256, 1) k_gemm() {
    extern __shared__ char smem[];
    uint32 sb = smem_u32(smem);
    int tid = threadIdx.x;
    int nb = blockIdx.x, mb = blockIdx.y, t = blockIdx.z;
    int it = t >> 3;

    const __half* Axh = g_xh16 + (size_t)(mb * 128) * 4096 + it * 512;
    const __half* Axl = g_xl16 + (size_t)(mb * 128) * 4096 + it * 512;
    size_t bbase = (size_t)t * 262144 + (size_t)(nb * 128) * 512;
    const __half* Bh = g_Gh + bbase;
    const __half* Bl = g_Gl + bbase;
    const __half* Bq = g_Qi + bbase;

    float acc_c[4][4][4];
    float acc_i[4][4][4];
    #pragma unroll
    for (int i = 0; i < 4; i++)
        #pragma unroll
        for (int j = 0; j < 4; j++)
            #pragma unroll
            for (int r = 0; r < 4; r++) { acc_c[i][j][r] = 0.f; acc_i[i][j][r] = 0.f; }

    auto issue = [&](int c) {
        uint32 sbuf = sb + (c & 1) * STAGE;
        int kk = c * 64;
        #pragma unroll
        for (int L0 = 0; L0 < 4; L0++) {
            int L = L0 * 256 + tid;            // 0..1023
            int r = L >> 3, ch = L & 7;        // row, 16B chunk (8 of them = 64 halves)
            uint32 d = sbuf + r * PITCH + ch * 16;
            int soA = r * 4096 + kk + ch * 8;
            int soB = r * 512  + kk + ch * 8;
            cpa16(d + OFF_XH, Axh + soA);
            cpa16(d + OFF_XL, Axl + soA);
            cpa16(d + OFF_GH, Bh + soB);
            cpa16(d + OFF_GL, Bl + soB);
            cpa16(d + OFF_QI, Bq + soB);
        }
        asm volatile("cp.async.commit_group;");
    };

    int lane = tid & 31, wid = tid >> 5;
    int wm0 = (wid >> 2) * 64, wn0 = (wid & 3) * 32;
    int wnid = wid & 3;
    int a_row = lane & 15;
    int a_koff = ((lane >> 4) & 1) * 16;
    int b_row = ((lane >> 4) & 1) * 8 + (lane & 7);
    int b_koff = ((lane >> 3) & 1) * 16;

    issue(0);
    for (int c = 0; c < 8; c++) {
        if (c < 7) {
            issue(c + 1);
            asm volatile("cp.async.wait_group 1;" ::: "memory");
        } else {
            asm volatile("cp.async.wait_group 0;" ::: "memory");
        }
        __syncthreads();
        uint32 sbuf = sb + (c & 1) * STAGE;

        #pragma unroll
        for (int ks = 0; ks < 4; ks++) {
            uint32 kb = ks * 32;
            uint32 axh[4][4], axl[4][4];
            #pragma unroll
            for (int i = 0; i < 4; i++) {
                uint32 ad = sbuf + (uint32)(wm0 + i * 16 + a_row) * PITCH + kb + a_koff;
                ldm_x4(axh[i], ad + OFF_XH);
                ldm_x4(axl[i], ad + OFF_XL);
            }
            uint32 gh[4][2], gl[4][2], qi[4][2];
            #pragma unroll
            for (int j2 = 0; j2 < 2; j2++) {
                uint32 bd = sbuf + (uint32)(wn0 + j2 * 16 + b_row) * PITCH + kb + b_koff;
                uint32 r4[4];
                ldm_x4(r4, bd + OFF_GH);
                gh[2*j2][0] = r4[0]; gh[2*j2][1] = r4[1];
                gh[2*j2+1][0] = r4[2]; gh[2*j2+1][1] = r4[3];
                ldm_x4(r4, bd + OFF_GL);
                gl[2*j2][0] = r4[0]; gl[2*j2][1] = r4[1];
                gl[2*j2+1][0] = r4[2]; gl[2*j2+1][1] = r4[3];
                ldm_x4(r4, bd + OFF_QI);
                qi[2*j2][0] = r4[0]; qi[2*j2][1] = r4[1];
                qi[2*j2+1][0] = r4[2]; qi[2*j2+1][1] = r4[3];
            }
            #pragma unroll
            for (int i = 0; i < 4; i++)
                #pragma unroll
                for (int j = 0; j < 4; j++) {
                    mma16816(acc_c[i][j], axh[i], gh[j]);
                    mma16816(acc_c[i][j], axh[i], gl[j]);
                    mma16816(acc_c[i][j], axl[i], gh[j]);
                    mma16816(acc_i[i][j], axh[i], qi[j]);
                }
        }
        __syncthreads();
    }

    // ---- epilogue: rescale currents, store, per-row stats ----
    int grp = lane >> 2, qd = lane & 3;
    size_t rowbase = (size_t)t * 1024 + (size_t)mb * 128;
    #pragma unroll
    for (int i = 0; i < 4; i++)
        #pragma unroll
        for (int j = 0; j < 4; j++)
            #pragma unroll
            for (int r = 0; r < 4; r++) acc_c[i][j][r] *= GINV;

    #pragma unroll
    for (int i = 0; i < 4; i++)
        #pragma unroll
        for (int h = 0; h < 2; h++) {
            int r = wm0 + i * 16 + h * 8 + grp;
            size_t gbb = (rowbase + r) * 512 + nb * 128 + wn0 + qd * 2;
            #pragma unroll
            for (int j = 0; j < 4; j++)
                *(float2*)&g_cur[gbb + j * 8] =
                    make_float2(acc_c[i][j][2*h], acc_c[i][j][2*h+1]);
        }

    float* stats = (float*)smem;   // [128 rows][4 nwarps][6]
    #pragma unroll
    for (int i = 0; i < 4; i++)
        #pragma unroll
        for (int h = 0; h < 2; h++) {
            float cs = 0.f, cmx = -FINF, cmn = FINF;
            float imx = -FINF, imn = FINF;
            #pragma unroll
            for (int j = 0; j < 4; j++) {
                float v0 = acc_c[i][j][2*h], v1 = acc_c[i][j][2*h+1];
                cs += v0 + v1; cmx = fmaxf(cmx, fmaxf(v0, v1)); cmn = fminf(cmn, fminf(v0, v1));
                float u0 = acc_i[i][j][2*h], u1 = acc_i[i][j][2*h+1];
                imx = fmaxf(imx, fmaxf(u0, u1)); imn = fminf(imn, fminf(u0, u1));
            }
            #pragma unroll
            for (int o = 1; o <= 2; o <<= 1) {
                cs  += __shfl_xor_sync(0xffffffffu, cs, o);
                cmx  = fmaxf(cmx, __shfl_xor_sync(0xffffffffu, cmx, o));
                cmn  = fminf(cmn, __shfl_xor_sync(0xffffffffu, cmn, o));
                imx  = fmaxf(imx, __shfl_xor_sync(0xffffffffu, imx, o));
                imn  = fminf(imn, __shfl_xor_sync(0xffffffffu, imn, o));
            }
            if (qd == 0) {
                int r = wm0 + i * 16 + h * 8 + grp;
                float* p = &stats[(r * 4 + wnid) * 6];
                p[0] = cs; p[1] = cmx; p[2] = cmn; p[3] = imx; p[4] = imn;
            }
        }
    __syncthreads();
    if (tid < 128) {
        float cs = 0.f, cmx = -FINF, cmn = FINF;
        float imx = -FINF, imn = FINF;
        #pragma unroll
        for (int wn = 0; wn < 4; wn++) {
            const float* p = &stats[(tid * 4 + wn) * 6];
            cs += p[0]; cmx = fmaxf(cmx, p[1]); cmn = fminf(cmn, p[2]);
            imx = fmaxf(imx, p[3]); imn = fminf(imn, p[4]);
        }
        float* p = &g_part[(((size_t)t * 4 + nb) * 1024 + (mb * 128 + tid)) * 6];
        p[0] = cs; p[1] = cmx; p[2] = cmn; p[3] = imx; p[4] = imn;
    }
}

// ---------------- kernel 5: combine ----------------
__global__ void __launch_bounds__(512) k_combine(const float* __restrict__ bias,
                                                 float* __restrict__ out) {
    int ot = blockIdx.x, b = blockIdx.y, j = threadIdx.x;
    float acc = 0.0f;
    #pragma unroll
    for (int it = 0; it < ITN; it++) {
        int t = it * 8 + ot;
        float cs = 0.f, cmx = -FINF, cmn = FINF, amx = -FINF, amn = FINF;
        #pragma unroll
        for (int nb = 0; nb < 4; nb++) {
            const float* p = &g_part[(((size_t)t * 4 + nb) * 1024 + b) * 6];
            cs += p[0]; cmx = fmaxf(cmx, p[1]); cmn = fminf(cmn, p[2]);
            amx = fmaxf(amx, p[3]); amn = fminf(amn, p[4]);
        }
        float cur = g_cur[((size_t)t * 1024 + b) * 512 + j];
        float xs = g_xsum[b * ITN + it];
        float idot = g_idot[((size_t)b * ITN + it) * 8 + ot];
        float cmean = cs * (1.0f / 512.0f);
        // exact ideal mean: GMIN*xsum + STEPQ*(x . colsum(q))/512
        float imean = __fadd_rn(__fmul_rn(STEPQ, idot * (1.0f / 512.0f)),
                                __fmul_rn(GMIN, xs));
        float coeff = __fdiv_rn(__fmul_rn(STEPQ, __fsub_rn(amx, amn)),
                                __fadd_rn(__fsub_rn(cmx, cmn), 1e-8f));
        float s = g_s[t], wmin = g_wmin[t];
        float off = __fmul_rn(xs, __fsub_rn(GMIN, __fmul_rn(s, wmin)));
        float val = __fadd_rn(__fmul_rn(__fsub_rn(cur, cmean), coeff), imean);
        acc += __fdiv_rn(__fsub_rn(val, off), s);
    }
    out[(size_t)b * 4096 + ot * TSZ + j] = __fadd_rn(acc, bias[ot * TSZ + j]);
}

// ---------------- launch ----------------
extern "C" void kernel_launch(void* const* d_in, const int* in_sizes, int n_in,
                              void* d_out, int out_size) {
    const float* x = nullptr; const float* w = nullptr; const float* bias = nullptr;
    for (int i = 0; i < n_in; i++) {
        if (in_sizes[i] == 1024 * 4096)      x    = (const float*)d_in[i];
        else if (in_sizes[i] == 4096 * 4096) w    = (const float*)d_in[i];
        else if (in_sizes[i] == 4096)        bias = (const float*)d_in[i];
    }
    float* out = (float*)d_out;

    cudaFuncSetAttribute(k_gemm, cudaFuncAttributeMaxDynamicSharedMemorySize, SMEM_GEMM);

    k_minmax_part<<<dim3(8, 64), 256>>>(w);
    k_minmax_fin<<<1, 64>>>();
    k_zero<<<32, 1024>>>();
    k_build<<<dim3(64, 64), 256>>>(w);
    k_xprep<<<8192, 128>>>(x);
    k_imean<<<dim3(8, 1024), 128>>>(x);
    k_gemm<<<dim3(4, 8, 64), 256, SMEM_GEMM>>>();
    k_combine<<<dim3(8, 1024), 512>>>(bias, out);
}

// round 8
// speedup vs baseline: 1.1264x; 1.1264x over previous
#include <cuda_runtime.h>
#include <cuda_fp16.h>
#include <cstdint>

// ---------------- problem constants ----------------
#define TSZ   512
#define NTILE 64
#define ITN   8

#define GMIN   1e-6f
#define GDIFF  ((float)(1.0e-4 - 1.0e-6))
#define STEPQ  ((float)((1.0e-4 - 1.0e-6) / 15.0))
#define FINF   3.402823466e38f
#define GSCALE 8192.0f
#define GINV   (1.0f / 8192.0f)

typedef unsigned int uint32;
typedef unsigned long long ull;

// ---------------- scratch (static device memory) ----------------
__device__ __half g_x16[(size_t)1024 * 4096];
__device__ __half g_Gh[(size_t)NTILE * TSZ * TSZ];   // geff*8192 hi, [t][n][k]
__device__ __half g_Gl[(size_t)NTILE * TSZ * TSZ];   // geff*8192 lo
__device__ __half g_Qi[(size_t)NTILE * TSZ * TSZ];   // quant code 0..15
__device__ float g_cur [(size_t)NTILE * 1024 * TSZ];  // 128 MB
__device__ float g_part[(size_t)NTILE * 4 * 1024 * 6];
__device__ float g_s[NTILE], g_wmin[NTILE];
__device__ float g_pmin[NTILE * 8], g_pmax[NTILE * 8];
__device__ float g_xsum[1024 * ITN];                  // sums of x~ (fp16-rounded x)
__device__ float g_qsum[NTILE * TSZ];                 // per (t,k) colsum of q (exact int)
__device__ float g_idot[(size_t)1024 * ITN * 8];      // x~ . qsum per (b,it,ot)

// ---------------- PTX helpers ----------------
__device__ __forceinline__ uint32 smem_u32(const void* p) {
    uint32 a;
    asm("{ .reg .u64 t; cvta.to.shared.u64 t, %1; cvt.u32.u64 %0, t; }" : "=r"(a) : "l"(p));
    return a;
}
__device__ __forceinline__ void cpa16(uint32 dst, const void* src) {
    asm volatile("cp.async.cg.shared.global [%0], [%1], 16;" :: "r"(dst), "l"(src));
}
__device__ __forceinline__ void ldm_x4(uint32* r, uint32 addr) {
    asm volatile("ldmatrix.sync.aligned.m8n8.x4.shared.b16 {%0,%1,%2,%3}, [%4];"
                 : "=r"(r[0]), "=r"(r[1]), "=r"(r[2]), "=r"(r[3]) : "r"(addr));
}
__device__ __forceinline__ void mma16816(float* c, const uint32* a, const uint32* b) {
    asm volatile(
        "mma.sync.aligned.m16n8k16.row.col.f32.f16.f16.f32 "
        "{%0,%1,%2,%3}, {%4,%5,%6,%7}, {%8,%9}, {%0,%1,%2,%3};"
        : "+f"(c[0]), "+f"(c[1]), "+f"(c[2]), "+f"(c[3])
        : "r"(a[0]), "r"(a[1]), "r"(a[2]), "r"(a[3]), "r"(b[0]), "r"(b[1]));
}

// ---------------- kernel 1a: per-tile min/max partials ----------------
__global__ void k_minmax_part(const float* __restrict__ w) {
    int t = blockIdx.y, chunk = blockIdx.x;
    int it = t >> 3, ot = t & 7;
    int tid = threadIdx.x;
    float mn = FINF, mx = -FINF;
    int base = chunk * 32768 + tid;
    #pragma unroll 4
    for (int k = 0; k < 128; k++) {
        int e = base + k * 256;
        int i = e >> 9, j = e & 511;
        float v = w[(size_t)(it * TSZ + i) * 4096 + ot * TSZ + j];
        mn = fminf(mn, v); mx = fmaxf(mx, v);
    }
    __shared__ float smn[256], smx[256];
    smn[tid] = mn; smx[tid] = mx;
    __syncthreads();
    for (int o = 128; o > 0; o >>= 1) {
        if (tid < o) {
            smn[tid] = fminf(smn[tid], smn[tid + o]);
            smx[tid] = fmaxf(smx[tid], smx[tid + o]);
        }
        __syncthreads();
    }
    if (tid == 0) { g_pmin[t * 8 + chunk] = smn[0]; g_pmax[t * 8 + chunk] = smx[0]; }
}

__global__ void k_minmax_fin() {
    int t = threadIdx.x;
    if (t < NTILE) {
        float mn = g_pmin[t * 8], mx = g_pmax[t * 8];
        #pragma unroll
        for (int c = 1; c < 8; c++) {
            mn = fminf(mn, g_pmin[t * 8 + c]);
            mx = fmaxf(mx, g_pmax[t * 8 + c]);
        }
        float denom = __fadd_rn(__fsub_rn(mx, mn), 1e-12f);
        g_s[t] = __fdiv_rn(GDIFF, denom);
        g_wmin[t] = mn;
    }
}

// ---------------- kernel 1c: zero qsum (graph-replay safe) ----------------
__global__ void k_zero() {
    g_qsum[blockIdx.x * 1024 + threadIdx.x] = 0.0f;
}

// ---------------- kernel 2: build Gh/Gl/Qi (fp16), [t][n][k]; accumulate colsum(q) ----------------
__global__ void __launch_bounds__(256) k_build(const float* __restrict__ w) {
    __shared__ __half sGh[64][72], sGl[64][72], sQi[64][72];
    int sub = blockIdx.x, t = blockIdx.y;
    int it = t >> 3, ot = t & 7;
    int ib = sub >> 3, jb = sub & 7;
    int i0 = ib * 64, j0 = jb * 64;
    int tid = threadIdx.x;
    float s = g_s[t], wmin = g_wmin[t];

    #pragma unroll
    for (int iter = 0; iter < 16; iter++) {
        int e = iter * 256 + tid;
        int i = e >> 6, j = e & 63;       // i: k, j: n
        float v = w[(size_t)(it * TSZ + i0 + i) * 4096 + ot * TSZ + j0 + j];
        // bit-exact reference op sequence:
        float t1   = __fsub_rn(v, wmin);
        float t2   = __fmul_rn(t1, s);
        float cond = __fadd_rn(t2, GMIN);
        float u    = __fsub_rn(cond, GMIN);
        float vv   = __fdiv_rn(u, STEPQ);
        float q    = rintf(vv);                       // 0..15, exact in fp16
        float cq   = __fadd_rn(__fmul_rn(q, STEPQ), GMIN);
        float inv  = __fdiv_rn(1.0f, cq);
        float rw   = (float)(2 * (513 + (j0 + j) - (i0 + i)));
        float ge   = __fdiv_rn(1.0f, __fadd_rn(inv, rw));
        float gs   = ge * GSCALE;                     // exact pow2 scale
        __half gh  = __float2half_rn(gs);
        __half gl  = __float2half_rn(__fsub_rn(gs, __half2float(gh)));
        sGh[j][i] = gh; sGl[j][i] = gl; sQi[j][i] = __float2half_rn(q);
    }
    __syncthreads();

    size_t obase = (size_t)t * 262144 + (size_t)j0 * 512 + i0;
    #pragma unroll
    for (int iter = 0; iter < 2; iter++) {
        int L = iter * 256 + tid;
        int n = L >> 3, k8 = (L & 7) * 8;
        size_t o = obase + (size_t)n * 512 + k8;
        *(uint4*)&g_Gh[o] = *(const uint4*)&sGh[n][k8];
        *(uint4*)&g_Gl[o] = *(const uint4*)&sGl[n][k8];
        *(uint4*)&g_Qi[o] = *(const uint4*)&sQi[n][k8];
    }

    // column sums of q over this block's 64 j's (exact small integers)
    if (tid < 64) {
        float sum = 0.0f;
        #pragma unroll
        for (int j = 0; j < 64; j++) sum += __half2float(sQi[j][tid]);
        atomicAdd(&g_qsum[t * 512 + i0 + tid], sum);
    }
}

// ---------------- kernel 2b: x -> fp16; xsum computed on ROUNDED values (consistency!) ----------------
__global__ void k_xprep(const float* __restrict__ x) {
    int blk = blockIdx.x;
    int b = blk >> 3, it = blk & 7;
    int tid = threadIdx.x;
    size_t base = (size_t)b * 4096 + it * TSZ + tid * 4;
    float4 v = *(const float4*)&x[base];
    __half h[4] = { __float2half_rn(v.x), __float2half_rn(v.y),
                    __float2half_rn(v.z), __float2half_rn(v.w) };
    *(ull*)&g_x16[base] = *(const ull*)h;
    // sum the fp16-rounded values so xsum matches the GEMM's effective input
    float s = __half2float(h[0]) + __half2float(h[1])
            + __half2float(h[2]) + __half2float(h[3]);
    #pragma unroll
    for (int o = 16; o > 0; o >>= 1) s += __shfl_down_sync(0xffffffffu, s, o);
    __shared__ float sm[4];
    if ((tid & 31) == 0) sm[tid >> 5] = s;
    __syncthreads();
    if (tid == 0) g_xsum[b * ITN + it] = sm[0] + sm[1] + sm[2] + sm[3];
}

// ---------------- kernel 3: exact ideal means on x~: idot[b][it][ot] = x~_row . qsum ----------------
__global__ void __launch_bounds__(128) k_imean() {
    int it = blockIdx.x, b = blockIdx.y, tid = threadIdx.x;
    size_t base = (size_t)b * 4096 + it * TSZ + tid * 4;
    ull hx = *(const ull*)&g_x16[base];
    __half hv[4]; *(ull*)hv = hx;
    float x0 = __half2float(hv[0]), x1 = __half2float(hv[1]);
    float x2 = __half2float(hv[2]), x3 = __half2float(hv[3]);
    float acc[8];
    #pragma unroll
    for (int ot = 0; ot < 8; ot++) {
        const float4 qv = *(const float4*)&g_qsum[(it * 8 + ot) * 512 + tid * 4];
        acc[ot] = x0 * qv.x + x1 * qv.y + x2 * qv.z + x3 * qv.w;
    }
    __shared__ float sm[4][8];
    #pragma unroll
    for (int ot = 0; ot < 8; ot++) {
        float s = acc[ot];
        #pragma unroll
        for (int o = 16; o > 0; o >>= 1) s += __shfl_down_sync(0xffffffffu, s, o);
        if ((tid & 31) == 0) sm[tid >> 5][ot] = s;
    }
    __syncthreads();
    if (tid < 8)
        g_idot[((size_t)b * ITN + it) * 8 + tid] =
            sm[0][tid] + sm[1][tid] + sm[2][tid] + sm[3][tid];
}

// ---------------- kernel 4: mma.sync GEMM, 3 passes, k-chunk 64, 2-stage ----------------
// passes: cur += x@Gh + x@Gl ; idl += x@Qi   (x = fp16-rounded, used consistently)
#define PITCH 144
#define ASZ   18432
#define OFF_X  0
#define OFF_GH (1 * ASZ)
#define OFF_GL (2 * ASZ)
#define OFF_QI (3 * ASZ)
#define STAGE  (4 * ASZ)
#define SMEM_GEMM (2 * STAGE)

__global__ void __launch_bounds__(256, 1) k_gemm() {
    extern __shared__ char smem[];
    uint32 sb = smem_u32(smem);
    int tid = threadIdx.x;
    int nb = blockIdx.x, mb = blockIdx.y, t = blockIdx.z;
    int it = t >> 3;

    const __half* Ax = g_x16 + (size_t)(mb * 128) * 4096 + it * 512;
    size_t bbase = (size_t)t * 262144 + (size_t)(nb * 128) * 512;
    const __half* Bh = g_Gh + bbase;
    const __half* Bl = g_Gl + bbase;
    const __half* Bq = g_Qi + bbase;

    float acc_c[4][4][4];
    float acc_i[4][4][4];
    #pragma unroll
    for (int i = 0; i < 4; i++)
        #pragma unroll
        for (int j = 0; j < 4; j++)
            #pragma unroll
            for (int r = 0; r < 4; r++) { acc_c[i][j][r] = 0.f; acc_i[i][j][r] = 0.f; }

    auto issue = [&](int c) {
        uint32 sbuf = sb + (c & 1) * STAGE;
        int kk = c * 64;
        #pragma unroll
        for (int L0 = 0; L0 < 4; L0++) {
            int L = L0 * 256 + tid;            // 0..1023
            int r = L >> 3, ch = L & 7;        // row, 16B chunk (8 = 64 halves)
            uint32 d = sbuf + r * PITCH + ch * 16;
            int soA = r * 4096 + kk + ch * 8;
            int soB = r * 512  + kk + ch * 8;
            cpa16(d + OFF_X,  Ax + soA);
            cpa16(d + OFF_GH, Bh + soB);
            cpa16(d + OFF_GL, Bl + soB);
            cpa16(d + OFF_QI, Bq + soB);
        }
        asm volatile("cp.async.commit_group;");
    };

    int lane = tid & 31, wid = tid >> 5;
    int wm0 = (wid >> 2) * 64, wn0 = (wid & 3) * 32;
    int wnid = wid & 3;
    int a_row = lane & 15;
    int a_koff = ((lane >> 4) & 1) * 16;
    int b_row = ((lane >> 4) & 1) * 8 + (lane & 7);
    int b_koff = ((lane >> 3) & 1) * 16;

    issue(0);
    for (int c = 0; c < 8; c++) {
        if (c < 7) {
            issue(c + 1);
            asm volatile("cp.async.wait_group 1;" ::: "memory");
        } else {
            asm volatile("cp.async.wait_group 0;" ::: "memory");
        }
        __syncthreads();
        uint32 sbuf = sb + (c & 1) * STAGE;

        #pragma unroll
        for (int ks = 0; ks < 4; ks++) {
            uint32 kb = ks * 32;
            uint32 ax[4][4];
            #pragma unroll
            for (int i = 0; i < 4; i++) {
                uint32 ad = sbuf + (uint32)(wm0 + i * 16 + a_row) * PITCH + kb + a_koff;
                ldm_x4(ax[i], ad + OFF_X);
            }
            uint32 gh[4][2], gl[4][2], qi[4][2];
            #pragma unroll
            for (int j2 = 0; j2 < 2; j2++) {
                uint32 bd = sbuf + (uint32)(wn0 + j2 * 16 + b_row) * PITCH + kb + b_koff;
                uint32 r4[4];
                ldm_x4(r4, bd + OFF_GH);
                gh[2*j2][0] = r4[0]; gh[2*j2][1] = r4[1];
                gh[2*j2+1][0] = r4[2]; gh[2*j2+1][1] = r4[3];
                ldm_x4(r4, bd + OFF_GL);
                gl[2*j2][0] = r4[0]; gl[2*j2][1] = r4[1];
                gl[2*j2+1][0] = r4[2]; gl[2*j2+1][1] = r4[3];
                ldm_x4(r4, bd + OFF_QI);
                qi[2*j2][0] = r4[0]; qi[2*j2][1] = r4[1];
                qi[2*j2+1][0] = r4[2]; qi[2*j2+1][1] = r4[3];
            }
            #pragma unroll
            for (int i = 0; i < 4; i++)
                #pragma unroll
                for (int j = 0; j < 4; j++) {
                    mma16816(acc_c[i][j], ax[i], gh[j]);
                    mma16816(acc_c[i][j], ax[i], gl[j]);
                    mma16816(acc_i[i][j], ax[i], qi[j]);
                }
        }
        __syncthreads();
    }

    // ---- epilogue: rescale currents, store, per-row stats ----
    int grp = lane >> 2, qd = lane & 3;
    size_t rowbase = (size_t)t * 1024 + (size_t)mb * 128;
    #pragma unroll
    for (int i = 0; i < 4; i++)
        #pragma unroll
        for (int j = 0; j < 4; j++)
            #pragma unroll
            for (int r = 0; r < 4; r++) acc_c[i][j][r] *= GINV;

    #pragma unroll
    for (int i = 0; i < 4; i++)
        #pragma unroll
        for (int h = 0; h < 2; h++) {
            int r = wm0 + i * 16 + h * 8 + grp;
            size_t gbb = (rowbase + r) * 512 + nb * 128 + wn0 + qd * 2;
            #pragma unroll
            for (int j = 0; j < 4; j++)
                *(float2*)&g_cur[gbb + j * 8] =
                    make_float2(acc_c[i][j][2*h], acc_c[i][j][2*h+1]);
        }

    float* stats = (float*)smem;   // [128 rows][4 nwarps][6]
    #pragma unroll
    for (int i = 0; i < 4; i++)
        #pragma unroll
        for (int h = 0; h < 2; h++) {
            float cs = 0.f, cmx = -FINF, cmn = FINF;
            float imx = -FINF, imn = FINF;
            #pragma unroll
            for (int j = 0; j < 4; j++) {
                float v0 = acc_c[i][j][2*h], v1 = acc_c[i][j][2*h+1];
                cs += v0 + v1; cmx = fmaxf(cmx, fmaxf(v0, v1)); cmn = fminf(cmn, fminf(v0, v1));
                float u0 = acc_i[i][j][2*h], u1 = acc_i[i][j][2*h+1];
                imx = fmaxf(imx, fmaxf(u0, u1)); imn = fminf(imn, fminf(u0, u1));
            }
            #pragma unroll
            for (int o = 1; o <= 2; o <<= 1) {
                cs  += __shfl_xor_sync(0xffffffffu, cs, o);
                cmx  = fmaxf(cmx, __shfl_xor_sync(0xffffffffu, cmx, o));
                cmn  = fminf(cmn, __shfl_xor_sync(0xffffffffu, cmn, o));
                imx  = fmaxf(imx, __shfl_xor_sync(0xffffffffu, imx, o));
                imn  = fminf(imn, __shfl_xor_sync(0xffffffffu, imn, o));
            }
            if (qd == 0) {
                int r = wm0 + i * 16 + h * 8 + grp;
                float* p = &stats[(r * 4 + wnid) * 6];
                p[0] = cs; p[1] = cmx; p[2] = cmn; p[3] = imx; p[4] = imn;
            }
        }
    __syncthreads();
    if (tid < 128) {
        float cs = 0.f, cmx = -FINF, cmn = FINF;
        float imx = -FINF, imn = FINF;
        #pragma unroll
        for (int wn = 0; wn < 4; wn++) {
            const float* p = &stats[(tid * 4 + wn) * 6];
            cs += p[0]; cmx = fmaxf(cmx, p[1]); cmn = fminf(cmn, p[2]);
            imx = fmaxf(imx, p[3]); imn = fminf(imn, p[4]);
        }
        float* p = &g_part[(((size_t)t * 4 + nb) * 1024 + (mb * 128 + tid)) * 6];
        p[0] = cs; p[1] = cmx; p[2] = cmn; p[3] = imx; p[4] = imn;
    }
}

// ---------------- kernel 5: combine ----------------
__global__ void __launch_bounds__(512) k_combine(const float* __restrict__ bias,
                                                 float* __restrict__ out) {
    int ot = blockIdx.x, b = blockIdx.y, j = threadIdx.x;
    float acc = 0.0f;
    #pragma unroll
    for (int it = 0; it < ITN; it++) {
        int t = it * 8 + ot;
        float cs = 0.f, cmx = -FINF, cmn = FINF, amx = -FINF, amn = FINF;
        #pragma unroll
        for (int nb = 0; nb < 4; nb++) {
            const float* p = &g_part[(((size_t)t * 4 + nb) * 1024 + b) * 6];
            cs += p[0]; cmx = fmaxf(cmx, p[1]); cmn = fminf(cmn, p[2]);
            amx = fmaxf(amx, p[3]); amn = fminf(amn, p[4]);
        }
        float cur = g_cur[((size_t)t * 1024 + b) * 512 + j];
        float xs = g_xsum[b * ITN + it];
        float idot = g_idot[((size_t)b * ITN + it) * 8 + ot];
        float cmean = cs * (1.0f / 512.0f);
        // exact ideal mean at x~: GMIN*xsum~ + STEPQ*(x~ . colsum(q))/512
        float imean = __fadd_rn(__fmul_rn(STEPQ, idot * (1.0f / 512.0f)),
                                __fmul_rn(GMIN, xs));
        float coeff = __fdiv_rn(__fmul_rn(STEPQ, __fsub_rn(amx, amn)),
                                __fadd_rn(__fsub_rn(cmx, cmn), 1e-8f));
        float s = g_s[t], wmin = g_wmin[t];
        float off = __fmul_rn(xs, __fsub_rn(GMIN, __fmul_rn(s, wmin)));
        float val = __fadd_rn(__fmul_rn(__fsub_rn(cur, cmean), coeff), imean);
        acc += __fdiv_rn(__fsub_rn(val, off), s);
    }
    out[(size_t)b * 4096 + ot * TSZ + j] = __fadd_rn(acc, bias[ot * TSZ + j]);
}

// ---------------- launch ----------------
extern "C" void kernel_launch(void* const* d_in, const int* in_sizes, int n_in,
                              void* d_out, int out_size) {
    const float* x = nullptr; const float* w = nullptr; const float* bias = nullptr;
    for (int i = 0; i < n_in; i++) {
        if (in_sizes[i] == 1024 * 4096)      x    = (const float*)d_in[i];
        else if (in_sizes[i] == 4096 * 4096) w    = (const float*)d_in[i];
        else if (in_sizes[i] == 4096)        bias = (const float*)d_in[i];
    }
    float* out = (float*)d_out;

    cudaFuncSetAttribute(k_gemm, cudaFuncAttributeMaxDynamicSharedMemorySize, SMEM_GEMM);

    k_minmax_part<<<dim3(8, 64), 256>>>(w);
    k_minmax_fin<<<1, 64>>>();
    k_zero<<<32, 1024>>>();
    k_build<<<dim3(64, 64), 256>>>(w);
    k_xprep<<<8192, 128>>>(x);
    k_imean<<<dim3(8, 1024), 128>>>();
    k_gemm<<<dim3(4, 8, 64), 256, SMEM_GEMM>>>();
    k_combine<<<dim3(8, 1024), 512>>>(bias, out);
}

// round 10
// speedup vs baseline: 1.1524x; 1.0230x over previous
#include <cuda_runtime.h>
#include <cuda_fp16.h>
#include <cstdint>

// ---------------- problem constants ----------------
#define TSZ   512
#define NTILE 64
#define ITN   8

#define GMIN   1e-6f
#define GDIFF  ((float)(1.0e-4 - 1.0e-6))
#define STEPQ  ((float)((1.0e-4 - 1.0e-6) / 15.0))
#define FINF   3.402823466e38f
#define GSCALE 8192.0f
#define GINV   (1.0f / 8192.0f)

typedef unsigned int uint32;
typedef unsigned long long ull;

// ---------------- scratch (static device memory) ----------------
__device__ __half g_x16[(size_t)1024 * 4096];
__device__ __half g_Gh[(size_t)NTILE * TSZ * TSZ];   // geff*8192 hi, [t][n][k]
__device__ __half g_Gl[(size_t)NTILE * TSZ * TSZ];   // geff*8192 lo
__device__ __half g_Qi[(size_t)NTILE * TSZ * TSZ];   // quant code 0..15
__device__ float g_cur [(size_t)NTILE * 1024 * TSZ];  // 128 MB
__device__ float g_part[(size_t)NTILE * 4 * 1024 * 6];
__device__ float g_s[NTILE], g_wmin[NTILE];
__device__ float g_pmin[NTILE * 8], g_pmax[NTILE * 8];
__device__ float g_xsum[1024 * ITN];                  // sums of x~ (fp16-rounded x)
__device__ float g_qsum[NTILE * TSZ];                 // per (t,k) colsum of q (exact int)
__device__ float g_idot[(size_t)1024 * ITN * 8];      // x~ . qsum per (b,it,ot)

// ---------------- PTX helpers ----------------
__device__ __forceinline__ uint32 smem_u32(const void* p) {
    uint32 a;
    asm("{ .reg .u64 t; cvta.to.shared.u64 t, %1; cvt.u32.u64 %0, t; }" : "=r"(a) : "l"(p));
    return a;
}
__device__ __forceinline__ void cpa16(uint32 dst, const void* src) {
    asm volatile("cp.async.cg.shared.global [%0], [%1], 16;" :: "r"(dst), "l"(src));
}
__device__ __forceinline__ void ldm_x4(uint32* r, uint32 addr) {
    asm volatile("ldmatrix.sync.aligned.m8n8.x4.shared.b16 {%0,%1,%2,%3}, [%4];"
                 : "=r"(r[0]), "=r"(r[1]), "=r"(r[2]), "=r"(r[3]) : "r"(addr));
}
__device__ __forceinline__ void mma16816(float* c, const uint32* a, const uint32* b) {
    asm volatile(
        "mma.sync.aligned.m16n8k16.row.col.f32.f16.f16.f32 "
        "{%0,%1,%2,%3}, {%4,%5,%6,%7}, {%8,%9}, {%0,%1,%2,%3};"
        : "+f"(c[0]), "+f"(c[1]), "+f"(c[2]), "+f"(c[3])
        : "r"(a[0]), "r"(a[1]), "r"(a[2]), "r"(a[3]), "r"(b[0]), "r"(b[1]));
}

// ---------------- kernel 1a: per-tile min/max partials ----------------
__global__ void k_minmax_part(const float* __restrict__ w) {
    int t = blockIdx.y, chunk = blockIdx.x;
    int it = t >> 3, ot = t & 7;
    int tid = threadIdx.x;
    float mn = FINF, mx = -FINF;
    int base = chunk * 32768 + tid;
    #pragma unroll 4
    for (int k = 0; k < 128; k++) {
        int e = base + k * 256;
        int i = e >> 9, j = e & 511;
        float v = w[(size_t)(it * TSZ + i) * 4096 + ot * TSZ + j];
        mn = fminf(mn, v); mx = fmaxf(mx, v);
    }
    __shared__ float smn[256], smx[256];
    smn[tid] = mn; smx[tid] = mx;
    __syncthreads();
    for (int o = 128; o > 0; o >>= 1) {
        if (tid < o) {
            smn[tid] = fminf(smn[tid], smn[tid + o]);
            smx[tid] = fmaxf(smx[tid], smx[tid + o]);
        }
        __syncthreads();
    }
    if (tid == 0) { g_pmin[t * 8 + chunk] = smn[0]; g_pmax[t * 8 + chunk] = smx[0]; }
}

__global__ void k_minmax_fin() {
    int t = threadIdx.x;
    if (t < NTILE) {
        float mn = g_pmin[t * 8], mx = g_pmax[t * 8];
        #pragma unroll
        for (int c = 1; c < 8; c++) {
            mn = fminf(mn, g_pmin[t * 8 + c]);
            mx = fmaxf(mx, g_pmax[t * 8 + c]);
        }
        float denom = __fadd_rn(__fsub_rn(mx, mn), 1e-12f);
        g_s[t] = __fdiv_rn(GDIFF, denom);
        g_wmin[t] = mn;
    }
}

// ---------------- kernel 1c: zero qsum (graph-replay safe) ----------------
__global__ void k_zero() {
    g_qsum[blockIdx.x * 1024 + threadIdx.x] = 0.0f;
}

// ---------------- kernel 2: build Gh/Gl/Qi (fp16), [t][n][k]; accumulate colsum(q) ----------------
__global__ void __launch_bounds__(256) k_build(const float* __restrict__ w) {
    __shared__ __half sGh[64][72], sGl[64][72], sQi[64][72];
    int sub = blockIdx.x, t = blockIdx.y;
    int it = t >> 3, ot = t & 7;
    int ib = sub >> 3, jb = sub & 7;
    int i0 = ib * 64, j0 = jb * 64;
    int tid = threadIdx.x;
    float s = g_s[t], wmin = g_wmin[t];

    #pragma unroll
    for (int iter = 0; iter < 16; iter++) {
        int e = iter * 256 + tid;
        int i = e >> 6, j = e & 63;       // i: k, j: n
        float v = w[(size_t)(it * TSZ + i0 + i) * 4096 + ot * TSZ + j0 + j];
        // bit-exact quantization bin selection (must match reference):
        float t1   = __fsub_rn(v, wmin);
        float t2   = __fmul_rn(t1, s);
        float cond = __fadd_rn(t2, GMIN);
        float u    = __fsub_rn(cond, GMIN);
        float vv   = __fdiv_rn(u, STEPQ);
        float q    = rintf(vv);                       // 0..15, exact in fp16
        // g_eff path feeds fp16 hi/lo -> fast reciprocals fine (2 ulp fp32)
        float cq   = __fadd_rn(__fmul_rn(q, STEPQ), GMIN);
        float inv  = __fdividef(1.0f, cq);
        float rw   = (float)(2 * (513 + (j0 + j) - (i0 + i)));
        float ge   = __fdividef(1.0f, inv + rw);
        float gs   = ge * GSCALE;                     // exact pow2 scale
        __half gh  = __float2half_rn(gs);
        __half gl  = __float2half_rn(__fsub_rn(gs, __half2float(gh)));
        sGh[j][i] = gh; sGl[j][i] = gl; sQi[j][i] = __float2half_rn(q);
    }
    __syncthreads();

    size_t obase = (size_t)t * 262144 + (size_t)j0 * 512 + i0;
    #pragma unroll
    for (int iter = 0; iter < 2; iter++) {
        int L = iter * 256 + tid;
        int n = L >> 3, k8 = (L & 7) * 8;
        size_t o = obase + (size_t)n * 512 + k8;
        *(uint4*)&g_Gh[o] = *(const uint4*)&sGh[n][k8];
        *(uint4*)&g_Gl[o] = *(const uint4*)&sGl[n][k8];
        *(uint4*)&g_Qi[o] = *(const uint4*)&sQi[n][k8];
    }

    // column sums of q over this block's 64 j's (exact small integers)
    if (tid < 64) {
        float sum = 0.0f;
        #pragma unroll
        for (int j = 0; j < 64; j++) sum += __half2float(sQi[j][tid]);
        atomicAdd(&g_qsum[t * 512 + i0 + tid], sum);
    }
}

// ---------------- kernel 2b: x -> fp16; xsum computed on ROUNDED values ----------------
__global__ void k_xprep(const float* __restrict__ x) {
    int blk = blockIdx.x;
    int b = blk >> 3, it = blk & 7;
    int tid = threadIdx.x;
    size_t base = (size_t)b * 4096 + it * TSZ + tid * 4;
    float4 v = *(const float4*)&x[base];
    __half h[4] = { __float2half_rn(v.x), __float2half_rn(v.y),
                    __float2half_rn(v.z), __float2half_rn(v.w) };
    *(ull*)&g_x16[base] = *(const ull*)h;
    float s = __half2float(h[0]) + __half2float(h[1])
            + __half2float(h[2]) + __half2float(h[3]);
    #pragma unroll
    for (int o = 16; o > 0; o >>= 1) s += __shfl_down_sync(0xffffffffu, s, o);
    __shared__ float sm[4];
    if ((tid & 31) == 0) sm[tid >> 5] = s;
    __syncthreads();
    if (tid == 0) g_xsum[b * ITN + it] = sm[0] + sm[1] + sm[2] + sm[3];
}

// ---------------- kernel 3: exact ideal means on x~ ----------------
__global__ void __launch_bounds__(128) k_imean() {
    int it = blockIdx.x, b = blockIdx.y, tid = threadIdx.x;
    size_t base = (size_t)b * 4096 + it * TSZ + tid * 4;
    ull hx = *(const ull*)&g_x16[base];
    __half hv[4]; *(ull*)hv = hx;
    float x0 = __half2float(hv[0]), x1 = __half2float(hv[1]);
    float x2 = __half2float(hv[2]), x3 = __half2float(hv[3]);
    float acc[8];
    #pragma unroll
    for (int ot = 0; ot < 8; ot++) {
        const float4 qv = *(const float4*)&g_qsum[(it * 8 + ot) * 512 + tid * 4];
        acc[ot] = x0 * qv.x + x1 * qv.y + x2 * qv.z + x3 * qv.w;
    }
    __shared__ float sm[4][8];
    #pragma unroll
    for (int ot = 0; ot < 8; ot++) {
        float s = acc[ot];
        #pragma unroll
        for (int o = 16; o > 0; o >>= 1) s += __shfl_down_sync(0xffffffffu, s, o);
        if ((tid & 31) == 0) sm[tid >> 5][ot] = s;
    }
    __syncthreads();
    if (tid < 8)
        g_idot[((size_t)b * ITN + it) * 8 + tid] =
            sm[0][tid] + sm[1][tid] + sm[2][tid] + sm[3][tid];
}

// ---------------- kernel 4: PERSISTENT mma.sync GEMM, 3 passes, k-chunk 64 ----------------
// 148 CTAs, each loops over work items (t,mb,nb); cp.async pipeline prefetches
// across item boundaries so it never drains. Stats use a dedicated smem region.
#define PITCH 144
#define ASZ   18432
#define OFF_X  0
#define OFF_GH (1 * ASZ)
#define OFF_GL (2 * ASZ)
#define OFF_QI (3 * ASZ)
#define STAGE  (4 * ASZ)
#define STATS_BYTES (128 * 4 * 6 * 4)
#define SMEM_GEMM (2 * STAGE + STATS_BYTES)
#define NITEMS 2048
#define GRID_P 148

__device__ __forceinline__ void decode_item(int item, const __half*& Ax,
                                            const __half*& Bh, const __half*& Bl,
                                            const __half*& Bq) {
    int nb = item & 3, mb = (item >> 2) & 7, t = item >> 5;
    Ax = g_x16 + (size_t)(mb * 128) * 4096 + (t >> 3) * 512;
    size_t bbase = (size_t)t * 262144 + (size_t)(nb * 128) * 512;
    Bh = g_Gh + bbase; Bl = g_Gl + bbase; Bq = g_Qi + bbase;
}

__global__ void __launch_bounds__(256, 1) k_gemm() {
    extern __shared__ char smem[];
    uint32 sb = smem_u32(smem);
    float* stats = (float*)(smem + 2 * STAGE);   // dedicated: no buffer conflict
    int tid = threadIdx.x;

    int lane = tid & 31, wid = tid >> 5;
    int wm0 = (wid >> 2) * 64, wn0 = (wid & 3) * 32;
    int wnid = wid & 3;
    int a_row = lane & 15;
    int a_koff = ((lane >> 4) & 1) * 16;
    int b_row = ((lane >> 4) & 1) * 8 + (lane & 7);
    int b_koff = ((lane >> 3) & 1) * 16;
    int grp = lane >> 2, qd = lane & 3;

    auto issue = [&](const __half* Ax, const __half* Bh, const __half* Bl,
                     const __half* Bq, int kk, uint32 sbuf) {
        #pragma unroll
        for (int L0 = 0; L0 < 4; L0++) {
            int L = L0 * 256 + tid;            // 0..1023
            int r = L >> 3, ch = L & 7;        // row, 16B chunk
            uint32 d = sbuf + r * PITCH + ch * 16;
            int soA = r * 4096 + kk + ch * 8;
            int soB = r * 512  + kk + ch * 8;
            cpa16(d + OFF_X,  Ax + soA);
            cpa16(d + OFF_GH, Bh + soB);
            cpa16(d + OFF_GL, Bl + soB);
            cpa16(d + OFF_QI, Bq + soB);
        }
        asm volatile("cp.async.commit_group;");
    };

    int item = blockIdx.x;
    const __half *Ax, *Bh, *Bl, *Bq;
    decode_item(item, Ax, Bh, Bl, Bq);
    issue(Ax, Bh, Bl, Bq, 0, sb);              // buffer 0
    int buf = 0;

    while (true) {
        float acc_c[4][4][4];
        float acc_i[4][4][4];
        #pragma unroll
        for (int i = 0; i < 4; i++)
            #pragma unroll
            for (int j = 0; j < 4; j++)
                #pragma unroll
                for (int r = 0; r < 4; r++) { acc_c[i][j][r] = 0.f; acc_i[i][j][r] = 0.f; }

        for (int c = 0; c < 8; c++) {
            // ---- prefetch next chunk (possibly next item's chunk 0) ----
            bool have;
            if (c < 7) {
                have = true;
                issue(Ax, Bh, Bl, Bq, (c + 1) * 64, sb + (buf ^ 1) * STAGE);
            } else {
                int ni = item + GRID_P;
                have = (ni < NITEMS);
                if (have) {
                    const __half *pA, *pH, *pL, *pQ;
                    decode_item(ni, pA, pH, pL, pQ);
                    issue(pA, pH, pL, pQ, 0, sb + (buf ^ 1) * STAGE);
                }
            }
            if (have) asm volatile("cp.async.wait_group 1;" ::: "memory");
            else      asm volatile("cp.async.wait_group 0;" ::: "memory");
            __syncthreads();
            uint32 sbuf = sb + buf * STAGE;

            #pragma unroll
            for (int ks = 0; ks < 4; ks++) {
                uint32 kb = ks * 32;
                uint32 ax[4][4];
                #pragma unroll
                for (int i = 0; i < 4; i++) {
                    uint32 ad = sbuf + (uint32)(wm0 + i * 16 + a_row) * PITCH + kb + a_koff;
                    ldm_x4(ax[i], ad + OFF_X);
                }
                uint32 gh[4][2], gl[4][2], qi[4][2];
                #pragma unroll
                for (int j2 = 0; j2 < 2; j2++) {
                    uint32 bd = sbuf + (uint32)(wn0 + j2 * 16 + b_row) * PITCH + kb + b_koff;
                    uint32 r4[4];
                    ldm_x4(r4, bd + OFF_GH);
                    gh[2*j2][0] = r4[0]; gh[2*j2][1] = r4[1];
                    gh[2*j2+1][0] = r4[2]; gh[2*j2+1][1] = r4[3];
                    ldm_x4(r4, bd + OFF_GL);
                    gl[2*j2][0] = r4[0]; gl[2*j2][1] = r4[1];
                    gl[2*j2+1][0] = r4[2]; gl[2*j2+1][1] = r4[3];
                    ldm_x4(r4, bd + OFF_QI);
                    qi[2*j2][0] = r4[0]; qi[2*j2][1] = r4[1];
                    qi[2*j2+1][0] = r4[2]; qi[2*j2+1][1] = r4[3];
                }
                #pragma unroll
                for (int i = 0; i < 4; i++)
                    #pragma unroll
                    for (int j = 0; j < 4; j++) {
                        mma16816(acc_c[i][j], ax[i], gh[j]);
                        mma16816(acc_c[i][j], ax[i], gl[j]);
                        mma16816(acc_i[i][j], ax[i], qi[j]);
                    }
            }
            buf ^= 1;
            __syncthreads();   // protect buffer we just read before next issue into it
        }

        // ---- epilogue for this item ----
        int nb = item & 3, mb = (item >> 2) & 7, t = item >> 5;
        size_t rowbase = (size_t)t * 1024 + (size_t)mb * 128;
        #pragma unroll
        for (int i = 0; i < 4; i++)
            #pragma unroll
            for (int j = 0; j < 4; j++)
                #pragma unroll
                for (int r = 0; r < 4; r++) acc_c[i][j][r] *= GINV;

        #pragma unroll
        for (int i = 0; i < 4; i++)
            #pragma unroll
            for (int h = 0; h < 2; h++) {
                int r = wm0 + i * 16 + h * 8 + grp;
                size_t gbb = (rowbase + r) * 512 + nb * 128 + wn0 + qd * 2;
                #pragma unroll
                for (int j = 0; j < 4; j++)
                    *(float2*)&g_cur[gbb + j * 8] =
                        make_float2(acc_c[i][j][2*h], acc_c[i][j][2*h+1]);
            }

        #pragma unroll
        for (int i = 0; i < 4; i++)
            #pragma unroll
            for (int h = 0; h < 2; h++) {
                float cs = 0.f, cmx = -FINF, cmn = FINF;
                float imx = -FINF, imn = FINF;
                #pragma unroll
                for (int j = 0; j < 4; j++) {
                    float v0 = acc_c[i][j][2*h], v1 = acc_c[i][j][2*h+1];
                    cs += v0 + v1; cmx = fmaxf(cmx, fmaxf(v0, v1)); cmn = fminf(cmn, fminf(v0, v1));
                    float u0 = acc_i[i][j][2*h], u1 = acc_i[i][j][2*h+1];
                    imx = fmaxf(imx, fmaxf(u0, u1)); imn = fminf(imn, fminf(u0, u1));
                }
                #pragma unroll
                for (int o = 1; o <= 2; o <<= 1) {
                    cs  += __shfl_xor_sync(0xffffffffu, cs, o);
                    cmx  = fmaxf(cmx, __shfl_xor_sync(0xffffffffu, cmx, o));
                    cmn  = fminf(cmn, __shfl_xor_sync(0xffffffffu, cmn, o));
                    imx  = fmaxf(imx, __shfl_xor_sync(0xffffffffu, imx, o));
                    imn  = fminf(imn, __shfl_xor_sync(0xffffffffu, imn, o));
                }
                if (qd == 0) {
                    int r = wm0 + i * 16 + h * 8 + grp;
                    float* p = &stats[(r * 4 + wnid) * 6];
                    p[0] = cs; p[1] = cmx; p[2] = cmn; p[3] = imx; p[4] = imn;
                }
            }
        __syncthreads();
        if (tid < 128) {
            float cs = 0.f, cmx = -FINF, cmn = FINF;
            float imx = -FINF, imn = FINF;
            #pragma unroll
            for (int wn = 0; wn < 4; wn++) {
                const float* p = &stats[(tid * 4 + wn) * 6];
                cs += p[0]; cmx = fmaxf(cmx, p[1]); cmn = fminf(cmn, p[2]);
                imx = fmaxf(imx, p[3]); imn = fminf(imn, p[4]);
            }
            float* p = &g_part[(((size_t)t * 4 + nb) * 1024 + (mb * 128 + tid)) * 6];
            p[0] = cs; p[1] = cmx; p[2] = cmn; p[3] = imx; p[4] = imn;
        }
        __syncthreads();   // stats smem reused next item

        item += GRID_P;
        if (item >= NITEMS) break;
        decode_item(item, Ax, Bh, Bl, Bq);
    }
}

// ---------------- kernel 5: combine ----------------
__global__ void __launch_bounds__(512) k_combine(const float* __restrict__ bias,
                                                 float* __restrict__ out) {
    int ot = blockIdx.x, b = blockIdx.y, j = threadIdx.x;
    float acc = 0.0f;
    #pragma unroll
    for (int it = 0; it < ITN; it++) {
        int t = it * 8 + ot;
        float cs = 0.f, cmx = -FINF, cmn = FINF, amx = -FINF, amn = FINF;
        #pragma unroll
        for (int nb = 0; nb < 4; nb++) {
            const float* p = &g_part[(((size_t)t * 4 + nb) * 1024 + b) * 6];
            cs += p[0]; cmx = fmaxf(cmx, p[1]); cmn = fminf(cmn, p[2]);
            amx = fmaxf(amx, p[3]); amn = fminf(amn, p[4]);
        }
        float cur = g_cur[((size_t)t * 1024 + b) * 512 + j];
        float xs = g_xsum[b * ITN + it];
        float idot = g_idot[((size_t)b * ITN + it) * 8 + ot];
        float cmean = cs * (1.0f / 512.0f);
        float imean = __fadd_rn(__fmul_rn(STEPQ, idot * (1.0f / 512.0f)),
                                __fmul_rn(GMIN, xs));
        float coeff = __fdiv_rn(__fmul_rn(STEPQ, __fsub_rn(amx, amn)),
                                __fadd_rn(__fsub_rn(cmx, cmn), 1e-8f));
        float s = g_s[t], wmin = g_wmin[t];
        float off = __fmul_rn(xs, __fsub_rn(GMIN, __fmul_rn(s, wmin)));
        float val = __fadd_rn(__fmul_rn(__fsub_rn(cur, cmean), coeff), imean);
        acc += __fdiv_rn(__fsub_rn(val, off), s);
    }
    out[(size_t)b * 4096 + ot * TSZ + j] = __fadd_rn(acc, bias[ot * TSZ + j]);
}

// ---------------- launch ----------------
extern "C" void kernel_launch(void* const* d_in, const int* in_sizes, int n_in,
                              void* d_out, int out_size) {
    const float* x = nullptr; const float* w = nullptr; const float* bias = nullptr;
    for (int i = 0; i < n_in; i++) {
        if (in_sizes[i] == 1024 * 4096)      x    = (const float*)d_in[i];
        else if (in_sizes[i] == 4096 * 4096) w    = (const float*)d_in[i];
        else if (in_sizes[i] == 4096)        bias = (const float*)d_in[i];
    }
    float* out = (float*)d_out;

    cudaFuncSetAttribute(k_gemm, cudaFuncAttributeMaxDynamicSharedMemorySize, SMEM_GEMM);

    k_minmax_part<<<dim3(8, 64), 256>>>(w);
    k_minmax_fin<<<1, 64>>>();
    k_zero<<<32, 1024>>>();
    k_build<<<dim3(64, 64), 256>>>(w);
    k_xprep<<<8192, 128>>>(x);
    k_imean<<<dim3(8, 1024), 128>>>();
    k_gemm<<<GRID_P, 256, SMEM_GEMM>>>();
    k_combine<<<dim3(8, 1024), 512>>>(bias, out);
}

// round 11
// speedup vs baseline: 1.1693x; 1.0147x over previous
#include <cuda_runtime.h>
#include <cuda_fp16.h>
#include <cstdint>

// ---------------- problem constants ----------------
#define TSZ   512
#define NTILE 64
#define ITN   8

#define GMIN   1e-6f
#define GDIFF  ((float)(1.0e-4 - 1.0e-6))
#define STEPQ  ((float)((1.0e-4 - 1.0e-6) / 15.0))
#define FINF   3.402823466e38f
#define GSCALE 8192.0f
#define GINV   (1.0f / 8192.0f)

typedef unsigned int uint32;
typedef unsigned long long ull;

// ---------------- scratch (static device memory) ----------------
__device__ __half g_x16[(size_t)1024 * 4096];
__device__ __half g_Gh[(size_t)NTILE * TSZ * TSZ];   // geff*8192 hi, [t][n][k]
__device__ __half g_Gl[(size_t)NTILE * TSZ * TSZ];   // geff*8192 lo
__device__ __half g_Qi[(size_t)NTILE * TSZ * TSZ];   // quant code 0..15
__device__ float g_cur [(size_t)NTILE * 1024 * TSZ];  // 128 MB
__device__ float g_part[(size_t)NTILE * 4 * 1024 * 6];
__device__ float g_s[NTILE], g_wmin[NTILE];
__device__ float g_pmin[NTILE * 8], g_pmax[NTILE * 8];
__device__ float g_xsum[1024 * ITN];                  // sums of x~ (fp16-rounded x)
__device__ float g_qsum[NTILE * TSZ];                 // per (t,k) colsum of q (exact int)
__device__ float g_idot[(size_t)1024 * ITN * 8];      // x~ . qsum per (b,it,ot)

// ---------------- PTX helpers ----------------
__device__ __forceinline__ uint32 smem_u32(const void* p) {
    uint32 a;
    asm("{ .reg .u64 t; cvta.to.shared.u64 t, %1; cvt.u32.u64 %0, t; }" : "=r"(a) : "l"(p));
    return a;
}
__device__ __forceinline__ void cpa16(uint32 dst, const void* src) {
    asm volatile("cp.async.cg.shared.global [%0], [%1], 16;" :: "r"(dst), "l"(src));
}
__device__ __forceinline__ void ldm_x4(uint32* r, uint32 addr) {
    asm volatile("ldmatrix.sync.aligned.m8n8.x4.shared.b16 {%0,%1,%2,%3}, [%4];"
                 : "=r"(r[0]), "=r"(r[1]), "=r"(r[2]), "=r"(r[3]) : "r"(addr));
}
__device__ __forceinline__ void mma16816(float* c, const uint32* a, const uint32* b) {
    asm volatile(
        "mma.sync.aligned.m16n8k16.row.col.f32.f16.f16.f32 "
        "{%0,%1,%2,%3}, {%4,%5,%6,%7}, {%8,%9}, {%0,%1,%2,%3};"
        : "+f"(c[0]), "+f"(c[1]), "+f"(c[2]), "+f"(c[3])
        : "r"(a[0]), "r"(a[1]), "r"(a[2]), "r"(a[3]), "r"(b[0]), "r"(b[1]));
}

// ---------------- kernel 1a: per-tile min/max partials ----------------
__global__ void k_minmax_part(const float* __restrict__ w) {
    int t = blockIdx.y, chunk = blockIdx.x;
    int it = t >> 3, ot = t & 7;
    int tid = threadIdx.x;
    float mn = FINF, mx = -FINF;
    int base = chunk * 32768 + tid;
    #pragma unroll 4
    for (int k = 0; k < 128; k++) {
        int e = base + k * 256;
        int i = e >> 9, j = e & 511;
        float v = w[(size_t)(it * TSZ + i) * 4096 + ot * TSZ + j];
        mn = fminf(mn, v); mx = fmaxf(mx, v);
    }
    __shared__ float smn[256], smx[256];
    smn[tid] = mn; smx[tid] = mx;
    __syncthreads();
    for (int o = 128; o > 0; o >>= 1) {
        if (tid < o) {
            smn[tid] = fminf(smn[tid], smn[tid + o]);
            smx[tid] = fmaxf(smx[tid], smx[tid + o]);
        }
        __syncthreads();
    }
    if (tid == 0) { g_pmin[t * 8 + chunk] = smn[0]; g_pmax[t * 8 + chunk] = smx[0]; }
}

__global__ void k_minmax_fin() {
    int t = threadIdx.x;
    if (t < NTILE) {
        float mn = g_pmin[t * 8], mx = g_pmax[t * 8];
        #pragma unroll
        for (int c = 1; c < 8; c++) {
            mn = fminf(mn, g_pmin[t * 8 + c]);
            mx = fmaxf(mx, g_pmax[t * 8 + c]);
        }
        float denom = __fadd_rn(__fsub_rn(mx, mn), 1e-12f);
        g_s[t] = __fdiv_rn(GDIFF, denom);
        g_wmin[t] = mn;
    }
}

// ---------------- kernel 1c: zero qsum (graph-replay safe) ----------------
__global__ void k_zero() {
    g_qsum[blockIdx.x * 1024 + threadIdx.x] = 0.0f;
}

// ---------------- kernel 2: build Gh/Gl/Qi (fp16), [t][n][k]; accumulate colsum(q) ----------------
__global__ void __launch_bounds__(256) k_build(const float* __restrict__ w) {
    __shared__ __half sGh[64][72], sGl[64][72], sQi[64][72];
    int sub = blockIdx.x, t = blockIdx.y;
    int it = t >> 3, ot = t & 7;
    int ib = sub >> 3, jb = sub & 7;
    int i0 = ib * 64, j0 = jb * 64;
    int tid = threadIdx.x;
    float s = g_s[t], wmin = g_wmin[t];

    #pragma unroll
    for (int iter = 0; iter < 16; iter++) {
        int e = iter * 256 + tid;
        int i = e >> 6, j = e & 63;       // i: k, j: n
        float v = w[(size_t)(it * TSZ + i0 + i) * 4096 + ot * TSZ + j0 + j];
        // bit-exact quantization bin selection (must match reference):
        float t1   = __fsub_rn(v, wmin);
        float t2   = __fmul_rn(t1, s);
        float cond = __fadd_rn(t2, GMIN);
        float u    = __fsub_rn(cond, GMIN);
        float vv   = __fdiv_rn(u, STEPQ);
        float q    = rintf(vv);                       // 0..15, exact in fp16
        // g_eff path feeds fp16 hi/lo -> fast reciprocals fine (2 ulp fp32)
        float cq   = __fadd_rn(__fmul_rn(q, STEPQ), GMIN);
        float inv  = __fdividef(1.0f, cq);
        float rw   = (float)(2 * (513 + (j0 + j) - (i0 + i)));
        float ge   = __fdividef(1.0f, inv + rw);
        float gs   = ge * GSCALE;                     // exact pow2 scale
        __half gh  = __float2half_rn(gs);
        __half gl  = __float2half_rn(__fsub_rn(gs, __half2float(gh)));
        sGh[j][i] = gh; sGl[j][i] = gl; sQi[j][i] = __float2half_rn(q);
    }
    __syncthreads();

    size_t obase = (size_t)t * 262144 + (size_t)j0 * 512 + i0;
    #pragma unroll
    for (int iter = 0; iter < 2; iter++) {
        int L = iter * 256 + tid;
        int n = L >> 3, k8 = (L & 7) * 8;
        size_t o = obase + (size_t)n * 512 + k8;
        *(uint4*)&g_Gh[o] = *(const uint4*)&sGh[n][k8];
        *(uint4*)&g_Gl[o] = *(const uint4*)&sGl[n][k8];
        *(uint4*)&g_Qi[o] = *(const uint4*)&sQi[n][k8];
    }

    // column sums of q over this block's 64 j's (exact small integers)
    if (tid < 64) {
        float sum = 0.0f;
        #pragma unroll
        for (int j = 0; j < 64; j++) sum += __half2float(sQi[j][tid]);
        atomicAdd(&g_qsum[t * 512 + i0 + tid], sum);
    }
}

// ---------------- kernel 2b: x -> fp16; xsum computed on ROUNDED values ----------------
__global__ void k_xprep(const float* __restrict__ x) {
    int blk = blockIdx.x;
    int b = blk >> 3, it = blk & 7;
    int tid = threadIdx.x;
    size_t base = (size_t)b * 4096 + it * TSZ + tid * 4;
    float4 v = *(const float4*)&x[base];
    __half h[4] = { __float2half_rn(v.x), __float2half_rn(v.y),
                    __float2half_rn(v.z), __float2half_rn(v.w) };
    *(ull*)&g_x16[base] = *(const ull*)h;
    float s = __half2float(h[0]) + __half2float(h[1])
            + __half2float(h[2]) + __half2float(h[3]);
    #pragma unroll
    for (int o = 16; o > 0; o >>= 1) s += __shfl_down_sync(0xffffffffu, s, o);
    __shared__ float sm[4];
    if ((tid & 31) == 0) sm[tid >> 5] = s;
    __syncthreads();
    if (tid == 0) g_xsum[b * ITN + it] = sm[0] + sm[1] + sm[2] + sm[3];
}

// ---------------- kernel 3: exact ideal means on x~ ----------------
__global__ void __launch_bounds__(128) k_imean() {
    int it = blockIdx.x, b = blockIdx.y, tid = threadIdx.x;
    size_t base = (size_t)b * 4096 + it * TSZ + tid * 4;
    ull hx = *(const ull*)&g_x16[base];
    __half hv[4]; *(ull*)hv = hx;
    float x0 = __half2float(hv[0]), x1 = __half2float(hv[1]);
    float x2 = __half2float(hv[2]), x3 = __half2float(hv[3]);
    float acc[8];
    #pragma unroll
    for (int ot = 0; ot < 8; ot++) {
        const float4 qv = *(const float4*)&g_qsum[(it * 8 + ot) * 512 + tid * 4];
        acc[ot] = x0 * qv.x + x1 * qv.y + x2 * qv.z + x3 * qv.w;
    }
    __shared__ float sm[4][8];
    #pragma unroll
    for (int ot = 0; ot < 8; ot++) {
        float s = acc[ot];
        #pragma unroll
        for (int o = 16; o > 0; o >>= 1) s += __shfl_down_sync(0xffffffffu, s, o);
        if ((tid & 31) == 0) sm[tid >> 5][ot] = s;
    }
    __syncthreads();
    if (tid < 8)
        g_idot[((size_t)b * ITN + it) * 8 + tid] =
            sm[0][tid] + sm[1][tid] + sm[2][tid] + sm[3][tid];
}

// ---------------- kernel 4: PERSISTENT GEMM, 3-stage pipeline, 1 barrier/chunk ----------------
#define PITCH 144
#define ASZ   18432
#define OFF_X  0
#define OFF_GH (1 * ASZ)
#define OFF_GL (2 * ASZ)
#define OFF_QI (3 * ASZ)
#define STAGE  (4 * ASZ)
#define NSTAGE 3
#define STATS_BYTES (128 * 4 * 5 * 4)
#define SMEM_GEMM (NSTAGE * STAGE + STATS_BYTES)
#define NITEMS 2048
#define GRID_P 148

__global__ void __launch_bounds__(256, 1) k_gemm() {
    extern __shared__ char smem[];
    uint32 sb = smem_u32(smem);
    float* stats = (float*)(smem + NSTAGE * STAGE);
    int tid = threadIdx.x;

    int lane = tid & 31, wid = tid >> 5;
    int wm0 = (wid >> 2) * 64, wn0 = (wid & 3) * 32;
    int wnid = wid & 3;
    int a_row = lane & 15;
    int a_koff = ((lane >> 4) & 1) * 16;
    int b_row = ((lane >> 4) & 1) * 8 + (lane & 7);
    int b_koff = ((lane >> 3) & 1) * 16;
    int grp = lane >> 2, qd = lane & 3;

    int bid = blockIdx.x;
    int nit = (NITEMS - bid + GRID_P - 1) / GRID_P;     // items for this CTA
    if (nit <= 0) return;
    int last_s = nit * 8 - 1;                            // last global chunk seq

    // issue chunk sequence s (item ii = s>>3, k-chunk c = s&7) into stage s%NSTAGE
    auto issue_seq = [&](int s) {
        int item = bid + (s >> 3) * GRID_P;
        int kk = (s & 7) * 64;
        int nb = item & 3, mb = (item >> 2) & 7, t = item >> 5;
        const __half* Ax = g_x16 + (size_t)(mb * 128) * 4096 + (t >> 3) * 512;
        size_t bbase = (size_t)t * 262144 + (size_t)(nb * 128) * 512;
        const __half* Bh = g_Gh + bbase;
        const __half* Bl = g_Gl + bbase;
        const __half* Bq = g_Qi + bbase;
        uint32 sbuf = sb + (uint32)(s % NSTAGE) * STAGE;
        #pragma unroll
        for (int L0 = 0; L0 < 4; L0++) {
            int L = L0 * 256 + tid;            // 0..1023
            int r = L >> 3, ch = L & 7;        // row, 16B chunk
            uint32 d = sbuf + r * PITCH + ch * 16;
            int soA = r * 4096 + kk + ch * 8;
            int soB = r * 512  + kk + ch * 8;
            cpa16(d + OFF_X,  Ax + soA);
            cpa16(d + OFF_GH, Bh + soB);
            cpa16(d + OFF_GL, Bl + soB);
            cpa16(d + OFF_QI, Bq + soB);
        }
        asm volatile("cp.async.commit_group;");
    };

    // prologue: 2 chunks in flight
    issue_seq(0);
    if (last_s >= 1) issue_seq(1);

    for (int ii = 0; ii < nit; ii++) {
        int item = bid + ii * GRID_P;

        float acc_c[4][4][4];
        float acc_i[4][4][4];
        #pragma unroll
        for (int i = 0; i < 4; i++)
            #pragma unroll
            for (int j = 0; j < 4; j++)
                #pragma unroll
                for (int r = 0; r < 4; r++) { acc_c[i][j][r] = 0.f; acc_i[i][j][r] = 0.f; }

        for (int c = 0; c < 8; c++) {
            int s = ii * 8 + c;
            // wait for chunk s (s+1 may still be in flight)
            if (s + 1 <= last_s) asm volatile("cp.async.wait_group 1;" ::: "memory");
            else                 asm volatile("cp.async.wait_group 0;" ::: "memory");
            // single barrier: data of s visible to all; all warps done reading stage (s-1)%3
            __syncthreads();
            // refill the stage freed by chunk s-1
            if (s + 2 <= last_s) issue_seq(s + 2);

            uint32 sbuf = sb + (uint32)(s % NSTAGE) * STAGE;
            #pragma unroll
            for (int ks = 0; ks < 4; ks++) {
                uint32 kb = ks * 32;
                uint32 ax[4][4];
                #pragma unroll
                for (int i = 0; i < 4; i++) {
                    uint32 ad = sbuf + (uint32)(wm0 + i * 16 + a_row) * PITCH + kb + a_koff;
                    ldm_x4(ax[i], ad + OFF_X);
                }
                uint32 gh[4][2], gl[4][2], qi[4][2];
                #pragma unroll
                for (int j2 = 0; j2 < 2; j2++) {
                    uint32 bd = sbuf + (uint32)(wn0 + j2 * 16 + b_row) * PITCH + kb + b_koff;
                    uint32 r4[4];
                    ldm_x4(r4, bd + OFF_GH);
                    gh[2*j2][0] = r4[0]; gh[2*j2][1] = r4[1];
                    gh[2*j2+1][0] = r4[2]; gh[2*j2+1][1] = r4[3];
                    ldm_x4(r4, bd + OFF_GL);
                    gl[2*j2][0] = r4[0]; gl[2*j2][1] = r4[1];
                    gl[2*j2+1][0] = r4[2]; gl[2*j2+1][1] = r4[3];
                    ldm_x4(r4, bd + OFF_QI);
                    qi[2*j2][0] = r4[0]; qi[2*j2][1] = r4[1];
                    qi[2*j2+1][0] = r4[2]; qi[2*j2+1][1] = r4[3];
                }
                // spread same-accumulator RAW deps: gh block, qi block, gl block
                #pragma unroll
                for (int i = 0; i < 4; i++) {
                    #pragma unroll
                    for (int j = 0; j < 4; j++) mma16816(acc_c[i][j], ax[i], gh[j]);
                    #pragma unroll
                    for (int j = 0; j < 4; j++) mma16816(acc_i[i][j], ax[i], qi[j]);
                    #pragma unroll
                    for (int j = 0; j < 4; j++) mma16816(acc_c[i][j], ax[i], gl[j]);
                }
            }
        }

        // ---- epilogue for this item (stats region separate from stages) ----
        int nb = item & 3, mb = (item >> 2) & 7, t = item >> 5;
        size_t rowbase = (size_t)t * 1024 + (size_t)mb * 128;
        #pragma unroll
        for (int i = 0; i < 4; i++)
            #pragma unroll
            for (int j = 0; j < 4; j++)
                #pragma unroll
                for (int r = 0; r < 4; r++) acc_c[i][j][r] *= GINV;

        #pragma unroll
        for (int i = 0; i < 4; i++)
            #pragma unroll
            for (int h = 0; h < 2; h++) {
                int r = wm0 + i * 16 + h * 8 + grp;
                size_t gbb = (rowbase + r) * 512 + nb * 128 + wn0 + qd * 2;
                #pragma unroll
                for (int j = 0; j < 4; j++)
                    *(float2*)&g_cur[gbb + j * 8] =
                        make_float2(acc_c[i][j][2*h], acc_c[i][j][2*h+1]);
            }

        #pragma unroll
        for (int i = 0; i < 4; i++)
            #pragma unroll
            for (int h = 0; h < 2; h++) {
                float cs = 0.f, cmx = -FINF, cmn = FINF;
                float imx = -FINF, imn = FINF;
                #pragma unroll
                for (int j = 0; j < 4; j++) {
                    float v0 = acc_c[i][j][2*h], v1 = acc_c[i][j][2*h+1];
                    cs += v0 + v1; cmx = fmaxf(cmx, fmaxf(v0, v1)); cmn = fminf(cmn, fminf(v0, v1));
                    float u0 = acc_i[i][j][2*h], u1 = acc_i[i][j][2*h+1];
                    imx = fmaxf(imx, fmaxf(u0, u1)); imn = fminf(imn, fminf(u0, u1));
                }
                #pragma unroll
                for (int o = 1; o <= 2; o <<= 1) {
                    cs  += __shfl_xor_sync(0xffffffffu, cs, o);
                    cmx  = fmaxf(cmx, __shfl_xor_sync(0xffffffffu, cmx, o));
                    cmn  = fminf(cmn, __shfl_xor_sync(0xffffffffu, cmn, o));
                    imx  = fmaxf(imx, __shfl_xor_sync(0xffffffffu, imx, o));
                    imn  = fminf(imn, __shfl_xor_sync(0xffffffffu, imn, o));
                }
                if (qd == 0) {
                    int r = wm0 + i * 16 + h * 8 + grp;
                    float* p = &stats[(r * 4 + wnid) * 5];
                    p[0] = cs; p[1] = cmx; p[2] = cmn; p[3] = imx; p[4] = imn;
                }
            }
        __syncthreads();
        if (tid < 128) {
            float cs = 0.f, cmx = -FINF, cmn = FINF;
            float imx = -FINF, imn = FINF;
            #pragma unroll
            for (int wn = 0; wn < 4; wn++) {
                const float* p = &stats[(tid * 4 + wn) * 5];
                cs += p[0]; cmx = fmaxf(cmx, p[1]); cmn = fminf(cmn, p[2]);
                imx = fmaxf(imx, p[3]); imn = fminf(imn, p[4]);
            }
            float* p = &g_part[(((size_t)t * 4 + nb) * 1024 + (mb * 128 + tid)) * 6];
            p[0] = cs; p[1] = cmx; p[2] = cmn; p[3] = imx; p[4] = imn;
        }
        __syncthreads();   // stats smem reused next item
    }
}

// ---------------- kernel 5: combine ----------------
__global__ void __launch_bounds__(512) k_combine(const float* __restrict__ bias,
                                                 float* __restrict__ out) {
    int ot = blockIdx.x, b = blockIdx.y, j = threadIdx.x;
    float acc = 0.0f;
    #pragma unroll
    for (int it = 0; it < ITN; it++) {
        int t = it * 8 + ot;
        float cs = 0.f, cmx = -FINF, cmn = FINF, amx = -FINF, amn = FINF;
        #pragma unroll
        for (int nb = 0; nb < 4; nb++) {
            const float* p = &g_part[(((size_t)t * 4 + nb) * 1024 + b) * 6];
            cs += p[0]; cmx = fmaxf(cmx, p[1]); cmn = fminf(cmn, p[2]);
            amx = fmaxf(amx, p[3]); amn = fminf(amn, p[4]);
        }
        float cur = g_cur[((size_t)t * 1024 + b) * 512 + j];
        float xs = g_xsum[b * ITN + it];
        float idot = g_idot[((size_t)b * ITN + it) * 8 + ot];
        float cmean = cs * (1.0f / 512.0f);
        float imean = __fadd_rn(__fmul_rn(STEPQ, idot * (1.0f / 512.0f)),
                                __fmul_rn(GMIN, xs));
        float coeff = __fdiv_rn(__fmul_rn(STEPQ, __fsub_rn(amx, amn)),
                                __fadd_rn(__fsub_rn(cmx, cmn), 1e-8f));
        float s = g_s[t], wmin = g_wmin[t];
        float off = __fmul_rn(xs, __fsub_rn(GMIN, __fmul_rn(s, wmin)));
        float val = __fadd_rn(__fmul_rn(__fsub_rn(cur, cmean), coeff), imean);
        acc += __fdiv_rn(__fsub_rn(val, off), s);
    }
    out[(size_t)b * 4096 + ot * TSZ + j] = __fadd_rn(acc, bias[ot * TSZ + j]);
}

// ---------------- launch ----------------
extern "C" void kernel_launch(void* const* d_in, const int* in_sizes, int n_in,
                              void* d_out, int out_size) {
    const float* x = nullptr; const float* w = nullptr; const float* bias = nullptr;
    for (int i = 0; i < n_in; i++) {
        if (in_sizes[i] == 1024 * 4096)      x    = (const float*)d_in[i];
        else if (in_sizes[i] == 4096 * 4096) w    = (const float*)d_in[i];
        else if (in_sizes[i] == 4096)        bias = (const float*)d_in[i];
    }
    float* out = (float*)d_out;

    cudaFuncSetAttribute(k_gemm, cudaFuncAttributeMaxDynamicSharedMemorySize, SMEM_GEMM);

    k_minmax_part<<<dim3(8, 64), 256>>>(w);
    k_minmax_fin<<<1, 64>>>();
    k_zero<<<32, 1024>>>();
    k_build<<<dim3(64, 64), 256>>>(w);
    k_xprep<<<8192, 128>>>(x);
    k_imean<<<dim3(8, 1024), 128>>>();
    k_gemm<<<GRID_P, 256, SMEM_GEMM>>>();
    k_combine<<<dim3(8, 1024), 512>>>(bias, out);
}

// round 12
// speedup vs baseline: 1.1951x; 1.0220x over previous
#include <cuda_runtime.h>
#include <cuda_fp16.h>
#include <cstdint>

// ---------------- problem constants ----------------
#define TSZ   512
#define NTILE 64
#define ITN   8

#define GMIN   1e-6f
#define GDIFF  ((float)(1.0e-4 - 1.0e-6))
#define STEPQ  ((float)((1.0e-4 - 1.0e-6) / 15.0))
#define FINF   3.402823466e38f
#define GSCALE 8192.0f
#define GINV   (1.0f / 8192.0f)

typedef unsigned int uint32;
typedef unsigned long long ull;

// ---------------- scratch (static device memory) ----------------
__device__ __half g_x16[(size_t)1024 * 4096];
__device__ __half g_Gh[(size_t)NTILE * TSZ * TSZ];   // geff*8192 hi, [t][n][k]
__device__ __half g_Gl[(size_t)NTILE * TSZ * TSZ];   // geff*8192 lo
__device__ __half g_Qi[(size_t)NTILE * TSZ * TSZ];   // quant code 0..15
__device__ float g_cur [(size_t)NTILE * 1024 * TSZ];  // 128 MB
__device__ float g_part[(size_t)NTILE * 4 * 1024 * 6];
__device__ float g_s[NTILE], g_wmin[NTILE];
__device__ float g_pmin[NTILE * 8], g_pmax[NTILE * 8];
__device__ float g_xsum[1024 * ITN];                  // sums of x~ (fp16-rounded x)
__device__ float g_qsum[NTILE * TSZ];                 // per (t,k) colsum of q (exact int)
__device__ float g_idot[(size_t)1024 * ITN * 8];      // x~ . qsum per (b,it,ot)

// ---------------- PTX helpers ----------------
__device__ __forceinline__ uint32 smem_u32(const void* p) {
    uint32 a;
    asm("{ .reg .u64 t; cvta.to.shared.u64 t, %1; cvt.u32.u64 %0, t; }" : "=r"(a) : "l"(p));
    return a;
}
__device__ __forceinline__ void cpa16(uint32 dst, const void* src) {
    asm volatile("cp.async.cg.shared.global [%0], [%1], 16;" :: "r"(dst), "l"(src));
}
__device__ __forceinline__ void ldm_x4(uint32* r, uint32 addr) {
    asm volatile("ldmatrix.sync.aligned.m8n8.x4.shared.b16 {%0,%1,%2,%3}, [%4];"
                 : "=r"(r[0]), "=r"(r[1]), "=r"(r[2]), "=r"(r[3]) : "r"(addr));
}
__device__ __forceinline__ void mma16816(float* c, const uint32* a, const uint32* b) {
    asm volatile(
        "mma.sync.aligned.m16n8k16.row.col.f32.f16.f16.f32 "
        "{%0,%1,%2,%3}, {%4,%5,%6,%7}, {%8,%9}, {%0,%1,%2,%3};"
        : "+f"(c[0]), "+f"(c[1]), "+f"(c[2]), "+f"(c[3])
        : "r"(a[0]), "r"(a[1]), "r"(a[2]), "r"(a[3]), "r"(b[0]), "r"(b[1]));
}

// ---------------- kernel 1a: per-tile min/max partials ----------------
__global__ void k_minmax_part(const float* __restrict__ w) {
    int t = blockIdx.y, chunk = blockIdx.x;
    int it = t >> 3, ot = t & 7;
    int tid = threadIdx.x;
    float mn = FINF, mx = -FINF;
    int base = chunk * 32768 + tid;
    #pragma unroll 4
    for (int k = 0; k < 128; k++) {
        int e = base + k * 256;
        int i = e >> 9, j = e & 511;
        float v = w[(size_t)(it * TSZ + i) * 4096 + ot * TSZ + j];
        mn = fminf(mn, v); mx = fmaxf(mx, v);
    }
    __shared__ float smn[256], smx[256];
    smn[tid] = mn; smx[tid] = mx;
    __syncthreads();
    for (int o = 128; o > 0; o >>= 1) {
        if (tid < o) {
            smn[tid] = fminf(smn[tid], smn[tid + o]);
            smx[tid] = fmaxf(smx[tid], smx[tid + o]);
        }
        __syncthreads();
    }
    if (tid == 0) { g_pmin[t * 8 + chunk] = smn[0]; g_pmax[t * 8 + chunk] = smx[0]; }
}

__global__ void k_minmax_fin() {
    int t = threadIdx.x;
    if (t < NTILE) {
        float mn = g_pmin[t * 8], mx = g_pmax[t * 8];
        #pragma unroll
        for (int c = 1; c < 8; c++) {
            mn = fminf(mn, g_pmin[t * 8 + c]);
            mx = fmaxf(mx, g_pmax[t * 8 + c]);
        }
        float denom = __fadd_rn(__fsub_rn(mx, mn), 1e-12f);
        g_s[t] = __fdiv_rn(GDIFF, denom);
        g_wmin[t] = mn;
    }
}

// ---------------- kernel 1c: zero qsum (graph-replay safe) ----------------
__global__ void k_zero() {
    g_qsum[blockIdx.x * 1024 + threadIdx.x] = 0.0f;
}

// ---------------- kernel 2: build Gh/Gl/Qi (fp16), [t][n][k]; accumulate colsum(q) ----------------
__global__ void __launch_bounds__(256) k_build(const float* __restrict__ w) {
    __shared__ __half sGh[64][72], sGl[64][72], sQi[64][72];
    int sub = blockIdx.x, t = blockIdx.y;
    int it = t >> 3, ot = t & 7;
    int ib = sub >> 3, jb = sub & 7;
    int i0 = ib * 64, j0 = jb * 64;
    int tid = threadIdx.x;
    float s = g_s[t], wmin = g_wmin[t];

    #pragma unroll
    for (int iter = 0; iter < 16; iter++) {
        int e = iter * 256 + tid;
        int i = e >> 6, j = e & 63;       // i: k, j: n
        float v = w[(size_t)(it * TSZ + i0 + i) * 4096 + ot * TSZ + j0 + j];
        // bit-exact quantization bin selection (must match reference):
        float t1   = __fsub_rn(v, wmin);
        float t2   = __fmul_rn(t1, s);
        float cond = __fadd_rn(t2, GMIN);
        float u    = __fsub_rn(cond, GMIN);
        float vv   = __fdiv_rn(u, STEPQ);
        float q    = rintf(vv);                       // 0..15, exact in fp16
        // g_eff path feeds fp16 hi/lo -> fast reciprocals fine (2 ulp fp32)
        float cq   = __fadd_rn(__fmul_rn(q, STEPQ), GMIN);
        float inv  = __fdividef(1.0f, cq);
        float rw   = (float)(2 * (513 + (j0 + j) - (i0 + i)));
        float ge   = __fdividef(1.0f, inv + rw);
        float gs   = ge * GSCALE;                     // exact pow2 scale
        __half gh  = __float2half_rn(gs);
        __half gl  = __float2half_rn(__fsub_rn(gs, __half2float(gh)));
        sGh[j][i] = gh; sGl[j][i] = gl; sQi[j][i] = __float2half_rn(q);
    }
    __syncthreads();

    size_t obase = (size_t)t * 262144 + (size_t)j0 * 512 + i0;
    #pragma unroll
    for (int iter = 0; iter < 2; iter++) {
        int L = iter * 256 + tid;
        int n = L >> 3, k8 = (L & 7) * 8;
        size_t o = obase + (size_t)n * 512 + k8;
        *(uint4*)&g_Gh[o] = *(const uint4*)&sGh[n][k8];
        *(uint4*)&g_Gl[o] = *(const uint4*)&sGl[n][k8];
        *(uint4*)&g_Qi[o] = *(const uint4*)&sQi[n][k8];
    }

    // column sums of q over this block's 64 j's (exact small integers)
    if (tid < 64) {
        float sum = 0.0f;
        #pragma unroll
        for (int j = 0; j < 64; j++) sum += __half2float(sQi[j][tid]);
        atomicAdd(&g_qsum[t * 512 + i0 + tid], sum);
    }
}

// ---------------- kernel 2b: x -> fp16; xsum computed on ROUNDED values ----------------
__global__ void k_xprep(const float* __restrict__ x) {
    int blk = blockIdx.x;
    int b = blk >> 3, it = blk & 7;
    int tid = threadIdx.x;
    size_t base = (size_t)b * 4096 + it * TSZ + tid * 4;
    float4 v = *(const float4*)&x[base];
    __half h[4] = { __float2half_rn(v.x), __float2half_rn(v.y),
                    __float2half_rn(v.z), __float2half_rn(v.w) };
    *(ull*)&g_x16[base] = *(const ull*)h;
    float s = __half2float(h[0]) + __half2float(h[1])
            + __half2float(h[2]) + __half2float(h[3]);
    #pragma unroll
    for (int o = 16; o > 0; o >>= 1) s += __shfl_down_sync(0xffffffffu, s, o);
    __shared__ float sm[4];
    if ((tid & 31) == 0) sm[tid >> 5] = s;
    __syncthreads();
    if (tid == 0) g_xsum[b * ITN + it] = sm[0] + sm[1] + sm[2] + sm[3];
}

// ---------------- kernel 3: exact ideal means on x~ ----------------
__global__ void __launch_bounds__(128) k_imean() {
    int it = blockIdx.x, b = blockIdx.y, tid = threadIdx.x;
    size_t base = (size_t)b * 4096 + it * TSZ + tid * 4;
    ull hx = *(const ull*)&g_x16[base];
    __half hv[4]; *(ull*)hv = hx;
    float x0 = __half2float(hv[0]), x1 = __half2float(hv[1]);
    float x2 = __half2float(hv[2]), x3 = __half2float(hv[3]);
    float acc[8];
    #pragma unroll
    for (int ot = 0; ot < 8; ot++) {
        const float4 qv = *(const float4*)&g_qsum[(it * 8 + ot) * 512 + tid * 4];
        acc[ot] = x0 * qv.x + x1 * qv.y + x2 * qv.z + x3 * qv.w;
    }
    __shared__ float sm[4][8];
    #pragma unroll
    for (int ot = 0; ot < 8; ot++) {
        float s = acc[ot];
        #pragma unroll
        for (int o = 16; o > 0; o >>= 1) s += __shfl_down_sync(0xffffffffu, s, o);
        if ((tid & 31) == 0) sm[tid >> 5][ot] = s;
    }
    __syncthreads();
    if (tid < 8)
        g_idot[((size_t)b * ITN + it) * 8 + tid] =
            sm[0][tid] + sm[1][tid] + sm[2][tid] + sm[3][tid];
}

// ---------------- kernel 4: PERSISTENT GEMM, 512 threads (4 warps/SMSP) ----------------
#define PITCH 144
#define ASZ   18432
#define OFF_X  0
#define OFF_GH (1 * ASZ)
#define OFF_GL (2 * ASZ)
#define OFF_QI (3 * ASZ)
#define STAGE  (4 * ASZ)
#define NSTAGE 3
#define STATS_BYTES (128 * 4 * 5 * 4)
#define SMEM_GEMM (NSTAGE * STAGE + STATS_BYTES)
#define NITEMS 2048
#define GRID_P 148

__global__ void __launch_bounds__(512, 1) k_gemm() {
    extern __shared__ char smem[];
    uint32 sb = smem_u32(smem);
    float* stats = (float*)(smem + NSTAGE * STAGE);
    int tid = threadIdx.x;

    int lane = tid & 31, wid = tid >> 5;          // 16 warps
    int wm0 = (wid >> 2) * 32;                    // 4 m-groups of 32 rows
    int wn0 = (wid & 3) * 32;                     // 4 n-groups of 32 cols
    int wnid = wid & 3;
    int a_row = lane & 15;
    int a_koff = ((lane >> 4) & 1) * 16;
    int b_row = ((lane >> 4) & 1) * 8 + (lane & 7);
    int b_koff = ((lane >> 3) & 1) * 16;
    int grp = lane >> 2, qd = lane & 3;

    int bid = blockIdx.x;
    int nit = (NITEMS - bid + GRID_P - 1) / GRID_P;
    if (nit <= 0) return;
    int last_s = nit * 8 - 1;

    auto issue_seq = [&](int s) {
        int item = bid + (s >> 3) * GRID_P;
        int kk = (s & 7) * 64;
        int nb = item & 3, mb = (item >> 2) & 7, t = item >> 5;
        const __half* Ax = g_x16 + (size_t)(mb * 128) * 4096 + (t >> 3) * 512;
        size_t bbase = (size_t)t * 262144 + (size_t)(nb * 128) * 512;
        const __half* Bh = g_Gh + bbase;
        const __half* Bl = g_Gl + bbase;
        const __half* Bq = g_Qi + bbase;
        uint32 sbuf = sb + (uint32)(s % NSTAGE) * STAGE;
        #pragma unroll
        for (int L0 = 0; L0 < 2; L0++) {
            int L = L0 * 512 + tid;            // 0..1023
            int r = L >> 3, ch = L & 7;        // row, 16B chunk
            uint32 d = sbuf + r * PITCH + ch * 16;
            int soA = r * 4096 + kk + ch * 8;
            int soB = r * 512  + kk + ch * 8;
            cpa16(d + OFF_X,  Ax + soA);
            cpa16(d + OFF_GH, Bh + soB);
            cpa16(d + OFF_GL, Bl + soB);
            cpa16(d + OFF_QI, Bq + soB);
        }
        asm volatile("cp.async.commit_group;");
    };

    issue_seq(0);
    if (last_s >= 1) issue_seq(1);

    for (int ii = 0; ii < nit; ii++) {
        int item = bid + ii * GRID_P;

        float acc_c[2][4][4];
        float acc_i[2][4][4];
        #pragma unroll
        for (int i = 0; i < 2; i++)
            #pragma unroll
            for (int j = 0; j < 4; j++)
                #pragma unroll
                for (int r = 0; r < 4; r++) { acc_c[i][j][r] = 0.f; acc_i[i][j][r] = 0.f; }

        for (int c = 0; c < 8; c++) {
            int s = ii * 8 + c;
            if (s + 1 <= last_s) asm volatile("cp.async.wait_group 1;" ::: "memory");
            else                 asm volatile("cp.async.wait_group 0;" ::: "memory");
            __syncthreads();
            if (s + 2 <= last_s) issue_seq(s + 2);

            uint32 sbuf = sb + (uint32)(s % NSTAGE) * STAGE;
            #pragma unroll
            for (int ks = 0; ks < 4; ks++) {
                uint32 kb = ks * 32;
                uint32 ax[2][4];
                #pragma unroll
                for (int i = 0; i < 2; i++) {
                    uint32 ad = sbuf + (uint32)(wm0 + i * 16 + a_row) * PITCH + kb + a_koff;
                    ldm_x4(ax[i], ad + OFF_X);
                }
                uint32 gh[4][2], gl[4][2], qi[4][2];
                #pragma unroll
                for (int j2 = 0; j2 < 2; j2++) {
                    uint32 bd = sbuf + (uint32)(wn0 + j2 * 16 + b_row) * PITCH + kb + b_koff;
                    uint32 r4[4];
                    ldm_x4(r4, bd + OFF_GH);
                    gh[2*j2][0] = r4[0]; gh[2*j2][1] = r4[1];
                    gh[2*j2+1][0] = r4[2]; gh[2*j2+1][1] = r4[3];
                    ldm_x4(r4, bd + OFF_GL);
                    gl[2*j2][0] = r4[0]; gl[2*j2][1] = r4[1];
                    gl[2*j2+1][0] = r4[2]; gl[2*j2+1][1] = r4[3];
                    ldm_x4(r4, bd + OFF_QI);
                    qi[2*j2][0] = r4[0]; qi[2*j2][1] = r4[1];
                    qi[2*j2+1][0] = r4[2]; qi[2*j2+1][1] = r4[3];
                }
                #pragma unroll
                for (int i = 0; i < 2; i++) {
                    #pragma unroll
                    for (int j = 0; j < 4; j++) mma16816(acc_c[i][j], ax[i], gh[j]);
                    #pragma unroll
                    for (int j = 0; j < 4; j++) mma16816(acc_i[i][j], ax[i], qi[j]);
                    #pragma unroll
                    for (int j = 0; j < 4; j++) mma16816(acc_c[i][j], ax[i], gl[j]);
                }
            }
        }

        // ---- epilogue for this item ----
        int nb = item & 3, mb = (item >> 2) & 7, t = item >> 5;
        size_t rowbase = (size_t)t * 1024 + (size_t)mb * 128;
        #pragma unroll
        for (int i = 0; i < 2; i++)
            #pragma unroll
            for (int j = 0; j < 4; j++)
                #pragma unroll
                for (int r = 0; r < 4; r++) acc_c[i][j][r] *= GINV;

        #pragma unroll
        for (int i = 0; i < 2; i++)
            #pragma unroll
            for (int h = 0; h < 2; h++) {
                int r = wm0 + i * 16 + h * 8 + grp;
                size_t gbb = (rowbase + r) * 512 + nb * 128 + wn0 + qd * 2;
                #pragma unroll
                for (int j = 0; j < 4; j++)
                    *(float2*)&g_cur[gbb + j * 8] =
                        make_float2(acc_c[i][j][2*h], acc_c[i][j][2*h+1]);
            }

        #pragma unroll
        for (int i = 0; i < 2; i++)
            #pragma unroll
            for (int h = 0; h < 2; h++) {
                float cs = 0.f, cmx = -FINF, cmn = FINF;
                float imx = -FINF, imn = FINF;
                #pragma unroll
                for (int j = 0; j < 4; j++) {
                    float v0 = acc_c[i][j][2*h], v1 = acc_c[i][j][2*h+1];
                    cs += v0 + v1; cmx = fmaxf(cmx, fmaxf(v0, v1)); cmn = fminf(cmn, fminf(v0, v1));
                    float u0 = acc_i[i][j][2*h], u1 = acc_i[i][j][2*h+1];
                    imx = fmaxf(imx, fmaxf(u0, u1)); imn = fminf(imn, fminf(u0, u1));
                }
                #pragma unroll
                for (int o = 1; o <= 2; o <<= 1) {
                    cs  += __shfl_xor_sync(0xffffffffu, cs, o);
                    cmx  = fmaxf(cmx, __shfl_xor_sync(0xffffffffu, cmx, o));
                    cmn  = fminf(cmn, __shfl_xor_sync(0xffffffffu, cmn, o));
                    imx  = fmaxf(imx, __shfl_xor_sync(0xffffffffu, imx, o));
                    imn  = fminf(imn, __shfl_xor_sync(0xffffffffu, imn, o));
                }
                if (qd == 0) {
                    int r = wm0 + i * 16 + h * 8 + grp;
                    float* p = &stats[(r * 4 + wnid) * 5];
                    p[0] = cs; p[1] = cmx; p[2] = cmn; p[3] = imx; p[4] = imn;
                }
            }
        __syncthreads();
        if (tid < 128) {
            float cs = 0.f, cmx = -FINF, cmn = FINF;
            float imx = -FINF, imn = FINF;
            #pragma unroll
            for (int wn = 0; wn < 4; wn++) {
                const float* p = &stats[(tid * 4 + wn) * 5];
                cs += p[0]; cmx = fmaxf(cmx, p[1]); cmn = fminf(cmn, p[2]);
                imx = fmaxf(imx, p[3]); imn = fminf(imn, p[4]);
            }
            float* p = &g_part[(((size_t)t * 4 + nb) * 1024 + (mb * 128 + tid)) * 6];
            p[0] = cs; p[1] = cmx; p[2] = cmn; p[3] = imx; p[4] = imn;
        }
        __syncthreads();   // stats smem reused next item
    }
}

// ---------------- kernel 5: combine ----------------
__global__ void __launch_bounds__(512) k_combine(const float* __restrict__ bias,
                                                 float* __restrict__ out) {
    int ot = blockIdx.x, b = blockIdx.y, j = threadIdx.x;
    float acc = 0.0f;
    #pragma unroll
    for (int it = 0; it < ITN; it++) {
        int t = it * 8 + ot;
        float cs = 0.f, cmx = -FINF, cmn = FINF, amx = -FINF, amn = FINF;
        #pragma unroll
        for (int nb = 0; nb < 4; nb++) {
            const float* p = &g_part[(((size_t)t * 4 + nb) * 1024 + b) * 6];
            cs += p[0]; cmx = fmaxf(cmx, p[1]); cmn = fminf(cmn, p[2]);
            amx = fmaxf(amx, p[3]); amn = fminf(amn, p[4]);
        }
        float cur = g_cur[((size_t)t * 1024 + b) * 512 + j];
        float xs = g_xsum[b * ITN + it];
        float idot = g_idot[((size_t)b * ITN + it) * 8 + ot];
        float cmean = cs * (1.0f / 512.0f);
        float imean = __fadd_rn(__fmul_rn(STEPQ, idot * (1.0f / 512.0f)),
                                __fmul_rn(GMIN, xs));
        float coeff = __fdiv_rn(__fmul_rn(STEPQ, __fsub_rn(amx, amn)),
                                __fadd_rn(__fsub_rn(cmx, cmn), 1e-8f));
        float s = g_s[t], wmin = g_wmin[t];
        float off = __fmul_rn(xs, __fsub_rn(GMIN, __fmul_rn(s, wmin)));
        float val = __fadd_rn(__fmul_rn(__fsub_rn(cur, cmean), coeff), imean);
        acc += __fdiv_rn(__fsub_rn(val, off), s);
    }
    out[(size_t)b * 4096 + ot * TSZ + j] = __fadd_rn(acc, bias[ot * TSZ + j]);
}

// ---------------- launch ----------------
extern "C" void kernel_launch(void* const* d_in, const int* in_sizes, int n_in,
                              void* d_out, int out_size) {
    const float* x = nullptr; const float* w = nullptr; const float* bias = nullptr;
    for (int i = 0; i < n_in; i++) {
        if (in_sizes[i] == 1024 * 4096)      x    = (const float*)d_in[i];
        else if (in_sizes[i] == 4096 * 4096) w    = (const float*)d_in[i];
        else if (in_sizes[i] == 4096)        bias = (const float*)d_in[i];
    }
    float* out = (float*)d_out;

    cudaFuncSetAttribute(k_gemm, cudaFuncAttributeMaxDynamicSharedMemorySize, SMEM_GEMM);

    k_minmax_part<<<dim3(8, 64), 256>>>(w);
    k_minmax_fin<<<1, 64>>>();
    k_zero<<<32, 1024>>>();
    k_build<<<dim3(64, 64), 256>>>(w);
    k_xprep<<<8192, 128>>>(x);
    k_imean<<<dim3(8, 1024), 128>>>();
    k_gemm<<<GRID_P, 512, SMEM_GEMM>>>();
    k_combine<<<dim3(8, 1024), 512>>>(bias, out);
}

// round 15
// speedup vs baseline: 1.2438x; 1.0407x over previous
#include <cuda_runtime.h>
#include <cuda_fp16.h>
#include <cstdint>

// ---------------- problem constants ----------------
#define TSZ   512
#define NTILE 64
#define ITN   8

#define GMIN   1e-6f
#define GDIFF  ((float)(1.0e-4 - 1.0e-6))
#define STEPQ  ((float)((1.0e-4 - 1.0e-6) / 15.0))
#define RSTEPQ ((float)(15.0 / (1.0e-4 - 1.0e-6)))
#define FINF   3.402823466e38f
#define GSCALE 8192.0f
#define GINV   (1.0f / 8192.0f)

typedef unsigned int uint32;
typedef unsigned long long ull;

// ---------------- scratch (static device memory) ----------------
__device__ __half g_x16[(size_t)1024 * 4096];
__device__ __half g_Gh[(size_t)NTILE * TSZ * TSZ];   // geff*8192 hi, [t][n][k]
__device__ __half g_Gl[(size_t)NTILE * TSZ * TSZ];   // geff*8192 lo
__device__ __half g_Qi[(size_t)NTILE * TSZ * TSZ];   // quant code 0..15
__device__ float g_cur [(size_t)NTILE * 1024 * TSZ];  // currents, fp32 (precision-critical)
__device__ float g_part[(size_t)NTILE * 4 * 1024 * 6];
__device__ float g_s[NTILE], g_wmin[NTILE];
__device__ float g_pmin[NTILE * 8], g_pmax[NTILE * 8];
__device__ float g_xsum[1024 * ITN];                  // sums of x~ (fp16-rounded x)
__device__ float g_qsum[NTILE * TSZ];                 // per (t,k) colsum of q (exact int)
__device__ float g_idot[(size_t)1024 * ITN * 8];      // x~ . qsum per (b,it,ot)

// ---------------- PTX helpers ----------------
__device__ __forceinline__ uint32 smem_u32(const void* p) {
    uint32 a;
    asm("{ .reg .u64 t; cvta.to.shared.u64 t, %1; cvt.u32.u64 %0, t; }" : "=r"(a) : "l"(p));
    return a;
}
__device__ __forceinline__ void cpa16(uint32 dst, const void* src) {
    asm volatile("cp.async.cg.shared.global [%0], [%1], 16;" :: "r"(dst), "l"(src));
}
__device__ __forceinline__ void ldm_x4(uint32* r, uint32 addr) {
    asm volatile("ldmatrix.sync.aligned.m8n8.x4.shared.b16 {%0,%1,%2,%3}, [%4];"
                 : "=r"(r[0]), "=r"(r[1]), "=r"(r[2]), "=r"(r[3]) : "r"(addr));
}
__device__ __forceinline__ void mma16816(float* c, const uint32* a, const uint32* b) {
    asm volatile(
        "mma.sync.aligned.m16n8k16.row.col.f32.f16.f16.f32 "
        "{%0,%1,%2,%3}, {%4,%5,%6,%7}, {%8,%9}, {%0,%1,%2,%3};"
        : "+f"(c[0]), "+f"(c[1]), "+f"(c[2]), "+f"(c[3])
        : "r"(a[0]), "r"(a[1]), "r"(a[2]), "r"(a[3]), "r"(b[0]), "r"(b[1]));
}

// ---------------- kernel 1a: per-tile min/max partials (float4, 8 accums) ----------------
__global__ void k_minmax_part(const float* __restrict__ w) {
    int t = blockIdx.y, chunk = blockIdx.x;
    int it = t >> 3, ot = t & 7;
    int tid = threadIdx.x;
    float mn0 = FINF, mn1 = FINF, mn2 = FINF, mn3 = FINF;
    float mx0 = -FINF, mx1 = -FINF, mx2 = -FINF, mx3 = -FINF;
    #pragma unroll 8
    for (int k = 0; k < 32; k++) {
        int e = (chunk * 8192 + k * 256 + tid) * 4;
        int i = e >> 9, j = e & 511;
        float4 v = *(const float4*)&w[(size_t)(it * TSZ + i) * 4096 + ot * TSZ + j];
        mn0 = fminf(mn0, v.x); mx0 = fmaxf(mx0, v.x);
        mn1 = fminf(mn1, v.y); mx1 = fmaxf(mx1, v.y);
        mn2 = fminf(mn2, v.z); mx2 = fmaxf(mx2, v.z);
        mn3 = fminf(mn3, v.w); mx3 = fmaxf(mx3, v.w);
    }
    float mn = fminf(fminf(mn0, mn1), fminf(mn2, mn3));
    float mx = fmaxf(fmaxf(mx0, mx1), fmaxf(mx2, mx3));
    #pragma unroll
    for (int o = 16; o > 0; o >>= 1) {
        mn = fminf(mn, __shfl_xor_sync(0xffffffffu, mn, o));
        mx = fmaxf(mx, __shfl_xor_sync(0xffffffffu, mx, o));
    }
    __shared__ float smn[8], smx[8];
    if ((tid & 31) == 0) { smn[tid >> 5] = mn; smx[tid >> 5] = mx; }
    __syncthreads();
    if (tid == 0) {
        float a = smn[0], b = smx[0];
        #pragma unroll
        for (int q = 1; q < 8; q++) { a = fminf(a, smn[q]); b = fmaxf(b, smx[q]); }
        g_pmin[t * 8 + chunk] = a; g_pmax[t * 8 + chunk] = b;
    }
}

__global__ void k_minmax_fin() {
    int t = threadIdx.x;
    if (t < NTILE) {
        float mn = g_pmin[t * 8], mx = g_pmax[t * 8];
        #pragma unroll
        for (int c = 1; c < 8; c++) {
            mn = fminf(mn, g_pmin[t * 8 + c]);
            mx = fmaxf(mx, g_pmax[t * 8 + c]);
        }
        float denom = __fadd_rn(__fsub_rn(mx, mn), 1e-12f);
        g_s[t] = __fdiv_rn(GDIFF, denom);
        g_wmin[t] = mn;
    }
}

// ---------------- kernel 1c: zero qsum (graph-replay safe) ----------------
__global__ void k_zero() {
    g_qsum[blockIdx.x * 1024 + threadIdx.x] = 0.0f;
}

// ---------------- kernel 2: build Gh/Gl/Qi (fp16), [t][n][k]; accumulate colsum(q) ----------------
__global__ void __launch_bounds__(256) k_build(const float* __restrict__ w) {
    __shared__ __half sGh[64][72], sGl[64][72], sQi[64][72];
    int sub = blockIdx.x, t = blockIdx.y;
    int it = t >> 3, ot = t & 7;
    int ib = sub >> 3, jb = sub & 7;
    int i0 = ib * 64, j0 = jb * 64;
    int tid = threadIdx.x;
    float s = g_s[t], wmin = g_wmin[t];

    #pragma unroll
    for (int iter = 0; iter < 16; iter++) {
        int e = iter * 256 + tid;
        int i = e >> 6, j = e & 63;       // i: k, j: n
        float v = w[(size_t)(it * TSZ + i0 + i) * 4096 + ot * TSZ + j0 + j];
        // quantization bin selection (reference op sequence; const-recip for /STEPQ):
        float t1   = __fsub_rn(v, wmin);
        float t2   = __fmul_rn(t1, s);
        float cond = __fadd_rn(t2, GMIN);
        float u    = __fsub_rn(cond, GMIN);
        float vv   = __fmul_rn(u, RSTEPQ);
        float q    = rintf(vv);                       // 0..15, exact in fp16
        // g_eff path feeds fp16 hi/lo -> fast reciprocals fine (2 ulp fp32)
        float cq   = __fadd_rn(__fmul_rn(q, STEPQ), GMIN);
        float inv  = __fdividef(1.0f, cq);
        float rw   = (float)(2 * (513 + (j0 + j) - (i0 + i)));
        float ge   = __fdividef(1.0f, inv + rw);
        float gs   = ge * GSCALE;                     // exact pow2 scale
        __half gh  = __float2half_rn(gs);
        __half gl  = __float2half_rn(__fsub_rn(gs, __half2float(gh)));
        sGh[j][i] = gh; sGl[j][i] = gl; sQi[j][i] = __float2half_rn(q);
    }
    __syncthreads();

    size_t obase = (size_t)t * 262144 + (size_t)j0 * 512 + i0;
    #pragma unroll
    for (int iter = 0; iter < 2; iter++) {
        int L = iter * 256 + tid;
        int n = L >> 3, k8 = (L & 7) * 8;
        size_t o = obase + (size_t)n * 512 + k8;
        *(uint4*)&g_Gh[o] = *(const uint4*)&sGh[n][k8];
        *(uint4*)&g_Gl[o] = *(const uint4*)&sGl[n][k8];
        *(uint4*)&g_Qi[o] = *(const uint4*)&sQi[n][k8];
    }

    // column sums of q over this block's 64 j's (exact small integers)
    if (tid < 64) {
        float sum = 0.0f;
        #pragma unroll
        for (int j = 0; j < 64; j++) sum += __half2float(sQi[j][tid]);
        atomicAdd(&g_qsum[t * 512 + i0 + tid], sum);
    }
}

// ---------------- kernel 3: fused x->fp16 + xsum~ + idot (runs AFTER k_build) ----------------
__global__ void __launch_bounds__(128) k_xprep_imean(const float* __restrict__ x) {
    int it = blockIdx.x, b = blockIdx.y, tid = threadIdx.x;
    size_t base = (size_t)b * 4096 + it * TSZ + tid * 4;
    float4 v = *(const float4*)&x[base];
    __half h[4] = { __float2half_rn(v.x), __float2half_rn(v.y),
                    __float2half_rn(v.z), __float2half_rn(v.w) };
    *(ull*)&g_x16[base] = *(const ull*)h;
    float x0 = __half2float(h[0]), x1 = __half2float(h[1]);
    float x2 = __half2float(h[2]), x3 = __half2float(h[3]);
    float s = x0 + x1 + x2 + x3;
    float acc[8];
    #pragma unroll
    for (int ot = 0; ot < 8; ot++) {
        const float4 qv = *(const float4*)&g_qsum[(it * 8 + ot) * 512 + tid * 4];
        acc[ot] = x0 * qv.x + x1 * qv.y + x2 * qv.z + x3 * qv.w;
    }
    __shared__ float sm[4][9];
    #pragma unroll
    for (int o = 16; o > 0; o >>= 1) s += __shfl_down_sync(0xffffffffu, s, o);
    if ((tid & 31) == 0) sm[tid >> 5][8] = s;
    #pragma unroll
    for (int ot = 0; ot < 8; ot++) {
        float a = acc[ot];
        #pragma unroll
        for (int o = 16; o > 0; o >>= 1) a += __shfl_down_sync(0xffffffffu, a, o);
        if ((tid & 31) == 0) sm[tid >> 5][ot] = a;
    }
    __syncthreads();
    if (tid < 8)
        g_idot[((size_t)b * ITN + it) * 8 + tid] =
            sm[0][tid] + sm[1][tid] + sm[2][tid] + sm[3][tid];
    if (tid == 8)
        g_xsum[b * ITN + it] = sm[0][8] + sm[1][8] + sm[2][8] + sm[3][8];
}

// ---------------- kernel 4: PERSISTENT GEMM, 512 threads (4 warps/SMSP) ----------------
#define PITCH 144
#define ASZ   18432
#define OFF_X  0
#define OFF_GH (1 * ASZ)
#define OFF_GL (2 * ASZ)
#define OFF_QI (3 * ASZ)
#define STAGE  (4 * ASZ)
#define NSTAGE 3
#define STATS_BYTES (128 * 4 * 5 * 4)
#define SMEM_GEMM (NSTAGE * STAGE + STATS_BYTES)
#define NITEMS 2048
#define GRID_P 148

__global__ void __launch_bounds__(512, 1) k_gemm() {
    extern __shared__ char smem[];
    uint32 sb = smem_u32(smem);
    float* stats = (float*)(smem + NSTAGE * STAGE);
    int tid = threadIdx.x;

    int lane = tid & 31, wid = tid >> 5;          // 16 warps
    int wm0 = (wid >> 2) * 32;
    int wn0 = (wid & 3) * 32;
    int wnid = wid & 3;
    int a_row = lane & 15;
    int a_koff = ((lane >> 4) & 1) * 16;
    int b_row = ((lane >> 4) & 1) * 8 + (lane & 7);
    int b_koff = ((lane >> 3) & 1) * 16;
    int grp = lane >> 2, qd = lane & 3;

    int bid = blockIdx.x;
    int nit = (NITEMS - bid + GRID_P - 1) / GRID_P;
    if (nit <= 0) return;
    int last_s = nit * 8 - 1;

    auto issue_seq = [&](int s) {
        int item = bid + (s >> 3) * GRID_P;
        int kk = (s & 7) * 64;
        int nb = item & 3, mb = (item >> 2) & 7, t = item >> 5;
        const __half* Ax = g_x16 + (size_t)(mb * 128) * 4096 + (t >> 3) * 512;
        size_t bbase = (size_t)t * 262144 + (size_t)(nb * 128) * 512;
        const __half* Bh = g_Gh + bbase;
        const __half* Bl = g_Gl + bbase;
        const __half* Bq = g_Qi + bbase;
        uint32 sbuf = sb + (uint32)(s % NSTAGE) * STAGE;
        #pragma unroll
        for (int L0 = 0; L0 < 2; L0++) {
            int L = L0 * 512 + tid;            // 0..1023
            int r = L >> 3, ch = L & 7;        // row, 16B chunk
            uint32 d = sbuf + r * PITCH + ch * 16;
            int soA = r * 4096 + kk + ch * 8;
            int soB = r * 512  + kk + ch * 8;
            cpa16(d + OFF_X,  Ax + soA);
            cpa16(d + OFF_GH, Bh + soB);
            cpa16(d + OFF_GL, Bl + soB);
            cpa16(d + OFF_QI, Bq + soB);
        }
        asm volatile("cp.async.commit_group;");
    };

    issue_seq(0);
    if (last_s >= 1) issue_seq(1);

    for (int ii = 0; ii < nit; ii++) {
        int item = bid + ii * GRID_P;

        float acc_c[2][4][4];
        float acc_i[2][4][4];
        #pragma unroll
        for (int i = 0; i < 2; i++)
            #pragma unroll
            for (int j = 0; j < 4; j++)
                #pragma unroll
                for (int r = 0; r < 4; r++) { acc_c[i][j][r] = 0.f; acc_i[i][j][r] = 0.f; }

        for (int c = 0; c < 8; c++) {
            int s = ii * 8 + c;
            if (s + 1 <= last_s) asm volatile("cp.async.wait_group 1;" ::: "memory");
            else                 asm volatile("cp.async.wait_group 0;" ::: "memory");
            __syncthreads();
            if (s + 2 <= last_s) issue_seq(s + 2);

            uint32 sbuf = sb + (uint32)(s % NSTAGE) * STAGE;
            #pragma unroll
            for (int ks = 0; ks < 4; ks++) {
                uint32 kb = ks * 32;
                uint32 ax[2][4];
                #pragma unroll
                for (int i = 0; i < 2; i++) {
                    uint32 ad = sbuf + (uint32)(wm0 + i * 16 + a_row) * PITCH + kb + a_koff;
                    ldm_x4(ax[i], ad + OFF_X);
                }
                uint32 gh[4][2], gl[4][2], qi[4][2];
                #pragma unroll
                for (int j2 = 0; j2 < 2; j2++) {
                    uint32 bd = sbuf + (uint32)(wn0 + j2 * 16 + b_row) * PITCH + kb + b_koff;
                    uint32 r4[4];
                    ldm_x4(r4, bd + OFF_GH);
                    gh[2*j2][0] = r4[0]; gh[2*j2][1] = r4[1];
                    gh[2*j2+1][0] = r4[2]; gh[2*j2+1][1] = r4[3];
                    ldm_x4(r4, bd + OFF_GL);
                    gl[2*j2][0] = r4[0]; gl[2*j2][1] = r4[1];
                    gl[2*j2+1][0] = r4[2]; gl[2*j2+1][1] = r4[3];
                    ldm_x4(r4, bd + OFF_QI);
                    qi[2*j2][0] = r4[0]; qi[2*j2][1] = r4[1];
                    qi[2*j2+1][0] = r4[2]; qi[2*j2+1][1] = r4[3];
                }
                #pragma unroll
                for (int i = 0; i < 2; i++) {
                    #pragma unroll
                    for (int j = 0; j < 4; j++) mma16816(acc_c[i][j], ax[i], gh[j]);
                    #pragma unroll
                    for (int j = 0; j < 4; j++) mma16816(acc_i[i][j], ax[i], qi[j]);
                    #pragma unroll
                    for (int j = 0; j < 4; j++) mma16816(acc_c[i][j], ax[i], gl[j]);
                }
            }
        }

        // ---- epilogue: rescale currents (GINV), store fp32, stats in FINAL units ----
        int nb = item & 3, mb = (item >> 2) & 7, t = item >> 5;
        size_t rowbase = (size_t)t * 1024 + (size_t)mb * 128;
        #pragma unroll
        for (int i = 0; i < 2; i++)
            #pragma unroll
            for (int j = 0; j < 4; j++)
                #pragma unroll
                for (int r = 0; r < 4; r++) acc_c[i][j][r] *= GINV;

        #pragma unroll
        for (int i = 0; i < 2; i++)
            #pragma unroll
            for (int h = 0; h < 2; h++) {
                int r = wm0 + i * 16 + h * 8 + grp;
                size_t gbb = (rowbase + r) * 512 + nb * 128 + wn0 + qd * 2;
                #pragma unroll
                for (int j = 0; j < 4; j++)
                    *(float2*)&g_cur[gbb + j * 8] =
                        make_float2(acc_c[i][j][2*h], acc_c[i][j][2*h+1]);
            }

        #pragma unroll
        for (int i = 0; i < 2; i++)
            #pragma unroll
            for (int h = 0; h < 2; h++) {
                float cs = 0.f, cmx = -FINF, cmn = FINF;
                float imx = -FINF, imn = FINF;
                #pragma unroll
                for (int j = 0; j < 4; j++) {
                    float v0 = acc_c[i][j][2*h], v1 = acc_c[i][j][2*h+1];
                    cs += v0 + v1; cmx = fmaxf(cmx, fmaxf(v0, v1)); cmn = fminf(cmn, fminf(v0, v1));
                    float u0 = acc_i[i][j][2*h], u1 = acc_i[i][j][2*h+1];
                    imx = fmaxf(imx, fmaxf(u0, u1)); imn = fminf(imn, fminf(u0, u1));
                }
                #pragma unroll
                for (int o = 1; o <= 2; o <<= 1) {
                    cs  += __shfl_xor_sync(0xffffffffu, cs, o);
                    cmx  = fmaxf(cmx, __shfl_xor_sync(0xffffffffu, cmx, o));
                    cmn  = fminf(cmn, __shfl_xor_sync(0xffffffffu, cmn, o));
                    imx  = fmaxf(imx, __shfl_xor_sync(0xffffffffu, imx, o));
                    imn  = fminf(imn, __shfl_xor_sync(0xffffffffu, imn, o));
                }
                if (qd == 0) {
                    int r = wm0 + i * 16 + h * 8 + grp;
                    float* p = &stats[(r * 4 + wnid) * 5];
                    p[0] = cs; p[1] = cmx; p[2] = cmn; p[3] = imx; p[4] = imn;
                }
            }
        __syncthreads();
        if (tid < 128) {
            float cs = 0.f, cmx = -FINF, cmn = FINF;
            float imx = -FINF, imn = FINF;
            #pragma unroll
            for (int wn = 0; wn < 4; wn++) {
                const float* p = &stats[(tid * 4 + wn) * 5];
                cs += p[0]; cmx = fmaxf(cmx, p[1]); cmn = fminf(cmn, p[2]);
                imx = fmaxf(imx, p[3]); imn = fminf(imn, p[4]);
            }
            float* p = &g_part[(((size_t)t * 4 + nb) * 1024 + (mb * 128 + tid)) * 6];
            p[0] = cs; p[1] = cmx; p[2] = cmn; p[3] = imx; p[4] = imn;
        }
        __syncthreads();   // stats smem reused next item
    }
}

// ---------------- kernel 5: combine (stats in FINAL units — matches epilogue) ----------------
__global__ void __launch_bounds__(512) k_combine(const float* __restrict__ bias,
                                                 float* __restrict__ out) {
    int ot = blockIdx.x, b = blockIdx.y, j = threadIdx.x;
    float acc = 0.0f;
    #pragma unroll
    for (int it = 0; it < ITN; it++) {
        int t = it * 8 + ot;
        float cs = 0.f, cmx = -FINF, cmn = FINF, amx = -FINF, amn = FINF;
        #pragma unroll
        for (int nb = 0; nb < 4; nb++) {
            const float* p = &g_part[(((size_t)t * 4 + nb) * 1024 + b) * 6];
            cs += p[0]; cmx = fmaxf(cmx, p[1]); cmn = fminf(cmn, p[2]);
            amx = fmaxf(amx, p[3]); amn = fminf(amn, p[4]);
        }
        float cur = g_cur[((size_t)t * 1024 + b) * 512 + j];
        float xs = g_xsum[b * ITN + it];
        float idot = g_idot[((size_t)b * ITN + it) * 8 + ot];
        float cmean = cs * (1.0f / 512.0f);
        float imean = __fadd_rn(__fmul_rn(STEPQ, idot * (1.0f / 512.0f)),
                                __fmul_rn(GMIN, xs));
        float coeff = __fdiv_rn(__fmul_rn(STEPQ, __fsub_rn(amx, amn)),
                                __fadd_rn(__fsub_rn(cmx, cmn), 1e-8f));
        float s = g_s[t], wmin = g_wmin[t];
        float off = __fmul_rn(xs, __fsub_rn(GMIN, __fmul_rn(s, wmin)));
        float val = __fadd_rn(__fmul_rn(__fsub_rn(cur, cmean), coeff), imean);
        acc += __fdiv_rn(__fsub_rn(val, off), s);
    }
    out[(size_t)b * 4096 + ot * TSZ + j] = __fadd_rn(acc, bias[ot * TSZ + j]);
}

// ---------------- launch ----------------
extern "C" void kernel_launch(void* const* d_in, const int* in_sizes, int n_in,
                              void* d_out, int out_size) {
    const float* x = nullptr; const float* w = nullptr; const float* bias = nullptr;
    for (int i = 0; i < n_in; i++) {
        if (in_sizes[i] == 1024 * 4096)      x    = (const float*)d_in[i];
        else if (in_sizes[i] == 4096 * 4096) w    = (const float*)d_in[i];
        else if (in_sizes[i] == 4096)        bias = (const float*)d_in[i];
    }
    float* out = (float*)d_out;

    cudaFuncSetAttribute(k_gemm, cudaFuncAttributeMaxDynamicSharedMemorySize, SMEM_GEMM);

    k_minmax_part<<<dim3(8, 64), 256>>>(w);
    k_minmax_fin<<<1, 64>>>();
    k_zero<<<32, 1024>>>();
    k_build<<<dim3(64, 64), 256>>>(w);
    k_xprep_imean<<<dim3(8, 1024), 128>>>(x);
    k_gemm<<<GRID_P, 512, SMEM_GEMM>>>();
    k_combine<<<dim3(8, 1024), 512>>>(bias, out);
}

// round 16
// speedup vs baseline: 1.2931x; 1.0397x over previous
#include <cuda_runtime.h>
#include <cuda_fp16.h>
#include <cstdint>

// ---------------- problem constants ----------------
#define TSZ   512
#define NTILE 64
#define ITN   8

#define GMIN   1e-6f
#define GDIFF  ((float)(1.0e-4 - 1.0e-6))
#define STEPQ  ((float)((1.0e-4 - 1.0e-6) / 15.0))
#define RSTEPQ ((float)(15.0 / (1.0e-4 - 1.0e-6)))
#define FINF   3.402823466e38f
#define GSCALE 8192.0f
#define GINV   (1.0f / 8192.0f)

typedef unsigned int uint32;
typedef unsigned long long ull;

// ---------------- scratch (static device memory) ----------------
__device__ __half g_x16[(size_t)1024 * 4096];
__device__ __half g_Gh[(size_t)NTILE * TSZ * TSZ];   // geff*8192 hi, [t][n][k]
__device__ __half g_Gl[(size_t)NTILE * TSZ * TSZ];   // geff*8192 lo
__device__ __half g_Qi[(size_t)NTILE * TSZ * TSZ];   // quant code 0..15
__device__ float g_cur [(size_t)NTILE * 1024 * TSZ];  // currents, fp32 (precision-critical)
__device__ float g_part[(size_t)NTILE * 4 * 1024 * 6];
__device__ float g_s[NTILE], g_wmin[NTILE];
__device__ float g_pmin[NTILE * 8], g_pmax[NTILE * 8];
__device__ float g_xsum[1024 * ITN];                  // sums of x~ (fp16-rounded x)
__device__ float g_qsum[NTILE * TSZ];                 // per (t,k) colsum of q (exact int)
__device__ float g_idot[(size_t)1024 * ITN * 8];      // x~ . qsum per (b,it,ot)

// ---------------- PTX helpers ----------------
__device__ __forceinline__ uint32 smem_u32(const void* p) {
    uint32 a;
    asm("{ .reg .u64 t; cvta.to.shared.u64 t, %1; cvt.u32.u64 %0, t; }" : "=r"(a) : "l"(p));
    return a;
}
__device__ __forceinline__ void cpa16(uint32 dst, const void* src) {
    asm volatile("cp.async.cg.shared.global [%0], [%1], 16;" :: "r"(dst), "l"(src));
}
__device__ __forceinline__ void ldm_x4(uint32* r, uint32 addr) {
    asm volatile("ldmatrix.sync.aligned.m8n8.x4.shared.b16 {%0,%1,%2,%3}, [%4];"
                 : "=r"(r[0]), "=r"(r[1]), "=r"(r[2]), "=r"(r[3]) : "r"(addr));
}
__device__ __forceinline__ void mma16816(float* c, const uint32* a, const uint32* b) {
    asm volatile(
        "mma.sync.aligned.m16n8k16.row.col.f32.f16.f16.f32 "
        "{%0,%1,%2,%3}, {%4,%5,%6,%7}, {%8,%9}, {%0,%1,%2,%3};"
        : "+f"(c[0]), "+f"(c[1]), "+f"(c[2]), "+f"(c[3])
        : "r"(a[0]), "r"(a[1]), "r"(a[2]), "r"(a[3]), "r"(b[0]), "r"(b[1]));
}

// ---------------- kernel 1a: per-tile min/max partials + qsum zeroing ----------------
__global__ void k_minmax_part(const float* __restrict__ w) {
    int t = blockIdx.y, chunk = blockIdx.x;
    int it = t >> 3, ot = t & 7;
    int tid = threadIdx.x;
    // zero qsum (this kernel strictly precedes k_build's atomics)
    if (tid < 64) g_qsum[t * 512 + chunk * 64 + tid] = 0.0f;
    float mn0 = FINF, mn1 = FINF, mn2 = FINF, mn3 = FINF;
    float mx0 = -FINF, mx1 = -FINF, mx2 = -FINF, mx3 = -FINF;
    #pragma unroll 8
    for (int k = 0; k < 32; k++) {
        int e = (chunk * 8192 + k * 256 + tid) * 4;
        int i = e >> 9, j = e & 511;
        float4 v = *(const float4*)&w[(size_t)(it * TSZ + i) * 4096 + ot * TSZ + j];
        mn0 = fminf(mn0, v.x); mx0 = fmaxf(mx0, v.x);
        mn1 = fminf(mn1, v.y); mx1 = fmaxf(mx1, v.y);
        mn2 = fminf(mn2, v.z); mx2 = fmaxf(mx2, v.z);
        mn3 = fminf(mn3, v.w); mx3 = fmaxf(mx3, v.w);
    }
    float mn = fminf(fminf(mn0, mn1), fminf(mn2, mn3));
    float mx = fmaxf(fmaxf(mx0, mx1), fmaxf(mx2, mx3));
    #pragma unroll
    for (int o = 16; o > 0; o >>= 1) {
        mn = fminf(mn, __shfl_xor_sync(0xffffffffu, mn, o));
        mx = fmaxf(mx, __shfl_xor_sync(0xffffffffu, mx, o));
    }
    __shared__ float smn[8], smx[8];
    if ((tid & 31) == 0) { smn[tid >> 5] = mn; smx[tid >> 5] = mx; }
    __syncthreads();
    if (tid == 0) {
        float a = smn[0], b = smx[0];
        #pragma unroll
        for (int q = 1; q < 8; q++) { a = fminf(a, smn[q]); b = fmaxf(b, smx[q]); }
        g_pmin[t * 8 + chunk] = a; g_pmax[t * 8 + chunk] = b;
    }
}

__global__ void k_minmax_fin() {
    int t = threadIdx.x;
    if (t < NTILE) {
        float mn = g_pmin[t * 8], mx = g_pmax[t * 8];
        #pragma unroll
        for (int c = 1; c < 8; c++) {
            mn = fminf(mn, g_pmin[t * 8 + c]);
            mx = fmaxf(mx, g_pmax[t * 8 + c]);
        }
        float denom = __fadd_rn(__fsub_rn(mx, mn), 1e-12f);
        g_s[t] = __fdiv_rn(GDIFF, denom);
        g_wmin[t] = mn;
    }
}

// ---------------- kernel 2: build Gh/Gl/Qi (fp16), [t][n][k]; STS.128 conflict-free ----------------
// Each thread: one n (j), 8 consecutive k (i); 8 coalesced loads, one STS.128 per array.
__global__ void __launch_bounds__(256) k_build(const float* __restrict__ w) {
    __shared__ __half sGh[64][72], sGl[64][72], sQi[64][72];
    int sub = blockIdx.x, t = blockIdx.y;
    int it = t >> 3, ot = t & 7;
    int ib = sub >> 3, jb = sub & 7;
    int i0 = ib * 64, j0 = jb * 64;
    int tid = threadIdx.x;
    float s = g_s[t], wmin = g_wmin[t];

    int j = tid & 63;          // n within subtile
    int i8b = tid >> 6;        // 0..3 (k-octet), iter adds 4

    #pragma unroll
    for (int iter = 0; iter < 2; iter++) {
        int i8 = i8b + iter * 4;             // 0..7
        __align__(16) __half hGh[8], hGl[8], hQi[8];
        #pragma unroll
        for (int l = 0; l < 8; l++) {
            int i = i8 * 8 + l;              // k within subtile
            float v = w[(size_t)(it * TSZ + i0 + i) * 4096 + ot * TSZ + j0 + j];
            // quantization bin selection (reference op sequence):
            float t1   = __fsub_rn(v, wmin);
            float t2   = __fmul_rn(t1, s);
            float cond = __fadd_rn(t2, GMIN);
            float u    = __fsub_rn(cond, GMIN);
            float vv   = __fmul_rn(u, RSTEPQ);
            float q    = rintf(vv);
            float cq   = __fadd_rn(__fmul_rn(q, STEPQ), GMIN);
            float inv  = __fdividef(1.0f, cq);
            float rw   = (float)(2 * (513 + (j0 + j) - (i0 + i)));
            float ge   = __fdividef(1.0f, inv + rw);
            float gs   = ge * GSCALE;
            __half gh  = __float2half_rn(gs);
            hGh[l] = gh;
            hGl[l] = __float2half_rn(__fsub_rn(gs, __half2float(gh)));
            hQi[l] = __float2half_rn(q);
        }
        *(uint4*)&sGh[j][i8 * 8] = *(const uint4*)hGh;
        *(uint4*)&sGl[j][i8 * 8] = *(const uint4*)hGl;
        *(uint4*)&sQi[j][i8 * 8] = *(const uint4*)hQi;
    }
    __syncthreads();

    size_t obase = (size_t)t * 262144 + (size_t)j0 * 512 + i0;
    #pragma unroll
    for (int iter = 0; iter < 2; iter++) {
        int L = iter * 256 + tid;
        int n = L >> 3, k8 = (L & 7) * 8;
        size_t o = obase + (size_t)n * 512 + k8;
        *(uint4*)&g_Gh[o] = *(const uint4*)&sGh[n][k8];
        *(uint4*)&g_Gl[o] = *(const uint4*)&sGl[n][k8];
        *(uint4*)&g_Qi[o] = *(const uint4*)&sQi[n][k8];
    }

    // column sums of q over this block's 64 j's (exact small integers)
    if (tid < 64) {
        float sum = 0.0f;
        #pragma unroll
        for (int jj = 0; jj < 64; jj++) sum += __half2float(sQi[jj][tid]);
        atomicAdd(&g_qsum[t * 512 + i0 + tid], sum);
    }
}

// ---------------- kernel 3: fused x->fp16 + xsum~ + idot (runs AFTER k_build) ----------------
__global__ void __launch_bounds__(128) k_xprep_imean(const float* __restrict__ x) {
    int it = blockIdx.x, b = blockIdx.y, tid = threadIdx.x;
    size_t base = (size_t)b * 4096 + it * TSZ + tid * 4;
    float4 v = *(const float4*)&x[base];
    __half h[4] = { __float2half_rn(v.x), __float2half_rn(v.y),
                    __float2half_rn(v.z), __float2half_rn(v.w) };
    *(ull*)&g_x16[base] = *(const ull*)h;
    float x0 = __half2float(h[0]), x1 = __half2float(h[1]);
    float x2 = __half2float(h[2]), x3 = __half2float(h[3]);
    float s = x0 + x1 + x2 + x3;
    float acc[8];
    #pragma unroll
    for (int ot = 0; ot < 8; ot++) {
        const float4 qv = *(const float4*)&g_qsum[(it * 8 + ot) * 512 + tid * 4];
        acc[ot] = x0 * qv.x + x1 * qv.y + x2 * qv.z + x3 * qv.w;
    }
    __shared__ float sm[4][9];
    #pragma unroll
    for (int o = 16; o > 0; o >>= 1) s += __shfl_down_sync(0xffffffffu, s, o);
    if ((tid & 31) == 0) sm[tid >> 5][8] = s;
    #pragma unroll
    for (int ot = 0; ot < 8; ot++) {
        float a = acc[ot];
        #pragma unroll
        for (int o = 16; o > 0; o >>= 1) a += __shfl_down_sync(0xffffffffu, a, o);
        if ((tid & 31) == 0) sm[tid >> 5][ot] = a;
    }
    __syncthreads();
    if (tid < 8)
        g_idot[((size_t)b * ITN + it) * 8 + tid] =
            sm[0][tid] + sm[1][tid] + sm[2][tid] + sm[3][tid];
    if (tid == 8)
        g_xsum[b * ITN + it] = sm[0][8] + sm[1][8] + sm[2][8] + sm[3][8];
}

// ---------------- kernel 4: PERSISTENT GEMM, 512 threads (4 warps/SMSP) ----------------
#define PITCH 144
#define ASZ   18432
#define OFF_X  0
#define OFF_GH (1 * ASZ)
#define OFF_GL (2 * ASZ)
#define OFF_QI (3 * ASZ)
#define STAGE  (4 * ASZ)
#define NSTAGE 3
#define STATS_BYTES (128 * 4 * 5 * 4)
#define SMEM_GEMM (NSTAGE * STAGE + STATS_BYTES)
#define NITEMS 2048
#define GRID_P 148

__global__ void __launch_bounds__(512, 1) k_gemm() {
    extern __shared__ char smem[];
    uint32 sb = smem_u32(smem);
    float* stats = (float*)(smem + NSTAGE * STAGE);
    int tid = threadIdx.x;

    int lane = tid & 31, wid = tid >> 5;          // 16 warps
    int wm0 = (wid >> 2) * 32;
    int wn0 = (wid & 3) * 32;
    int wnid = wid & 3;
    int a_row = lane & 15;
    int a_koff = ((lane >> 4) & 1) * 16;
    int b_row = ((lane >> 4) & 1) * 8 + (lane & 7);
    int b_koff = ((lane >> 3) & 1) * 16;
    int grp = lane >> 2, qd = lane & 3;

    int bid = blockIdx.x;
    int nit = (NITEMS - bid + GRID_P - 1) / GRID_P;
    if (nit <= 0) return;
    int last_s = nit * 8 - 1;

    auto issue_seq = [&](int s) {
        int item = bid + (s >> 3) * GRID_P;
        int kk = (s & 7) * 64;
        int nb = item & 3, mb = (item >> 2) & 7, t = item >> 5;
        const __half* Ax = g_x16 + (size_t)(mb * 128) * 4096 + (t >> 3) * 512;
        size_t bbase = (size_t)t * 262144 + (size_t)(nb * 128) * 512;
        const __half* Bh = g_Gh + bbase;
        const __half* Bl = g_Gl + bbase;
        const __half* Bq = g_Qi + bbase;
        uint32 sbuf = sb + (uint32)(s % NSTAGE) * STAGE;
        #pragma unroll
        for (int L0 = 0; L0 < 2; L0++) {
            int L = L0 * 512 + tid;            // 0..1023
            int r = L >> 3, ch = L & 7;        // row, 16B chunk
            uint32 d = sbuf + r * PITCH + ch * 16;
            int soA = r * 4096 + kk + ch * 8;
            int soB = r * 512  + kk + ch * 8;
            cpa16(d + OFF_X,  Ax + soA);
            cpa16(d + OFF_GH, Bh + soB);
            cpa16(d + OFF_GL, Bl + soB);
            cpa16(d + OFF_QI, Bq + soB);
        }
        asm volatile("cp.async.commit_group;");
    };

    issue_seq(0);
    if (last_s >= 1) issue_seq(1);

    for (int ii = 0; ii < nit; ii++) {
        int item = bid + ii * GRID_P;

        float acc_c[2][4][4];
        float acc_i[2][4][4];
        #pragma unroll
        for (int i = 0; i < 2; i++)
            #pragma unroll
            for (int j = 0; j < 4; j++)
                #pragma unroll
                for (int r = 0; r < 4; r++) { acc_c[i][j][r] = 0.f; acc_i[i][j][r] = 0.f; }

        for (int c = 0; c < 8; c++) {
            int s = ii * 8 + c;
            if (s + 1 <= last_s) asm volatile("cp.async.wait_group 1;" ::: "memory");
            else                 asm volatile("cp.async.wait_group 0;" ::: "memory");
            __syncthreads();
            if (s + 2 <= last_s) issue_seq(s + 2);

            uint32 sbuf = sb + (uint32)(s % NSTAGE) * STAGE;
            #pragma unroll
            for (int ks = 0; ks < 4; ks++) {
                uint32 kb = ks * 32;
                uint32 ax[2][4];
                #pragma unroll
                for (int i = 0; i < 2; i++) {
                    uint32 ad = sbuf + (uint32)(wm0 + i * 16 + a_row) * PITCH + kb + a_koff;
                    ldm_x4(ax[i], ad + OFF_X);
                }
                uint32 gh[4][2], gl[4][2], qi[4][2];
                #pragma unroll
                for (int j2 = 0; j2 < 2; j2++) {
                    uint32 bd = sbuf + (uint32)(wn0 + j2 * 16 + b_row) * PITCH + kb + b_koff;
                    uint32 r4[4];
                    ldm_x4(r4, bd + OFF_GH);
                    gh[2*j2][0] = r4[0]; gh[2*j2][1] = r4[1];
                    gh[2*j2+1][0] = r4[2]; gh[2*j2+1][1] = r4[3];
                    ldm_x4(r4, bd + OFF_GL);
                    gl[2*j2][0] = r4[0]; gl[2*j2][1] = r4[1];
                    gl[2*j2+1][0] = r4[2]; gl[2*j2+1][1] = r4[3];
                    ldm_x4(r4, bd + OFF_QI);
                    qi[2*j2][0] = r4[0]; qi[2*j2][1] = r4[1];
                    qi[2*j2+1][0] = r4[2]; qi[2*j2+1][1] = r4[3];
                }
                #pragma unroll
                for (int i = 0; i < 2; i++) {
                    #pragma unroll
                    for (int j = 0; j < 4; j++) mma16816(acc_c[i][j], ax[i], gh[j]);
                    #pragma unroll
                    for (int j = 0; j < 4; j++) mma16816(acc_i[i][j], ax[i], qi[j]);
                    #pragma unroll
                    for (int j = 0; j < 4; j++) mma16816(acc_c[i][j], ax[i], gl[j]);
                }
            }
        }

        // ---- epilogue: rescale currents (GINV), store fp32, stats in FINAL units ----
        int nb = item & 3, mb = (item >> 2) & 7, t = item >> 5;
        size_t rowbase = (size_t)t * 1024 + (size_t)mb * 128;
        #pragma unroll
        for (int i = 0; i < 2; i++)
            #pragma unroll
            for (int j = 0; j < 4; j++)
                #pragma unroll
                for (int r = 0; r < 4; r++) acc_c[i][j][r] *= GINV;

        #pragma unroll
        for (int i = 0; i < 2; i++)
            #pragma unroll
            for (int h = 0; h < 2; h++) {
                int r = wm0 + i * 16 + h * 8 + grp;
                size_t gbb = (rowbase + r) * 512 + nb * 128 + wn0 + qd * 2;
                #pragma unroll
                for (int j = 0; j < 4; j++)
                    *(float2*)&g_cur[gbb + j * 8] =
                        make_float2(acc_c[i][j][2*h], acc_c[i][j][2*h+1]);
            }

        #pragma unroll
        for (int i = 0; i < 2; i++)
            #pragma unroll
            for (int h = 0; h < 2; h++) {
                float cs = 0.f, cmx = -FINF, cmn = FINF;
                float imx = -FINF, imn = FINF;
                #pragma unroll
                for (int j = 0; j < 4; j++) {
                    float v0 = acc_c[i][j][2*h], v1 = acc_c[i][j][2*h+1];
                    cs += v0 + v1; cmx = fmaxf(cmx, fmaxf(v0, v1)); cmn = fminf(cmn, fminf(v0, v1));
                    float u0 = acc_i[i][j][2*h], u1 = acc_i[i][j][2*h+1];
                    imx = fmaxf(imx, fmaxf(u0, u1)); imn = fminf(imn, fminf(u0, u1));
                }
                #pragma unroll
                for (int o = 1; o <= 2; o <<= 1) {
                    cs  += __shfl_xor_sync(0xffffffffu, cs, o);
                    cmx  = fmaxf(cmx, __shfl_xor_sync(0xffffffffu, cmx, o));
                    cmn  = fminf(cmn, __shfl_xor_sync(0xffffffffu, cmn, o));
                    imx  = fmaxf(imx, __shfl_xor_sync(0xffffffffu, imx, o));
                    imn  = fminf(imn, __shfl_xor_sync(0xffffffffu, imn, o));
                }
                if (qd == 0) {
                    int r = wm0 + i * 16 + h * 8 + grp;
                    float* p = &stats[(r * 4 + wnid) * 5];
                    p[0] = cs; p[1] = cmx; p[2] = cmn; p[3] = imx; p[4] = imn;
                }
            }
        __syncthreads();
        if (tid < 128) {
            float cs = 0.f, cmx = -FINF, cmn = FINF;
            float imx = -FINF, imn = FINF;
            #pragma unroll
            for (int wn = 0; wn < 4; wn++) {
                const float* p = &stats[(tid * 4 + wn) * 5];
                cs += p[0]; cmx = fmaxf(cmx, p[1]); cmn = fminf(cmn, p[2]);
                imx = fmaxf(imx, p[3]); imn = fminf(imn, p[4]);
            }
            float* p = &g_part[(((size_t)t * 4 + nb) * 1024 + (mb * 128 + tid)) * 6];
            p[0] = cs; p[1] = cmx; p[2] = cmn; p[3] = imx; p[4] = imn;
        }
        __syncthreads();   // stats smem reused next item
    }
}

// ---------------- kernel 5: combine (stats in FINAL units — matches epilogue) ----------------
__global__ void __launch_bounds__(512) k_combine(const float* __restrict__ bias,
                                                 float* __restrict__ out) {
    int ot = blockIdx.x, b = blockIdx.y, j = threadIdx.x;
    float acc = 0.0f;
    #pragma unroll
    for (int it = 0; it < ITN; it++) {
        int t = it * 8 + ot;
        float cs = 0.f, cmx = -FINF, cmn = FINF, amx = -FINF, amn = FINF;
        #pragma unroll
        for (int nb = 0; nb < 4; nb++) {
            const float* p = &g_part[(((size_t)t * 4 + nb) * 1024 + b) * 6];
            cs += p[0]; cmx = fmaxf(cmx, p[1]); cmn = fminf(cmn, p[2]);
            amx = fmaxf(amx, p[3]); amn = fminf(amn, p[4]);
        }
        float cur = g_cur[((size_t)t * 1024 + b) * 512 + j];
        float xs = g_xsum[b * ITN + it];
        float idot = g_idot[((size_t)b * ITN + it) * 8 + ot];
        float cmean = cs * (1.0f / 512.0f);
        float imean = __fadd_rn(__fmul_rn(STEPQ, idot * (1.0f / 512.0f)),
                                __fmul_rn(GMIN, xs));
        float coeff = __fdiv_rn(__fmul_rn(STEPQ, __fsub_rn(amx, amn)),
                                __fadd_rn(__fsub_rn(cmx, cmn), 1e-8f));
        float s = g_s[t], wmin = g_wmin[t];
        float off = __fmul_rn(xs, __fsub_rn(GMIN, __fmul_rn(s, wmin)));
        float val = __fadd_rn(__fmul_rn(__fsub_rn(cur, cmean), coeff), imean);
        acc += __fdiv_rn(__fsub_rn(val, off), s);
    }
    out[(size_t)b * 4096 + ot * TSZ + j] = __fadd_rn(acc, bias[ot * TSZ + j]);
}

// ---------------- launch ----------------
extern "C" void kernel_launch(void* const* d_in, const int* in_sizes, int n_in,
                              void* d_out, int out_size) {
    const float* x = nullptr; const float* w = nullptr; const float* bias = nullptr;
    for (int i = 0; i < n_in; i++) {
        if (in_sizes[i] == 1024 * 4096)      x    = (const float*)d_in[i];
        else if (in_sizes[i] == 4096 * 4096) w    = (const float*)d_in[i];
        else if (in_sizes[i] == 4096)        bias = (const float*)d_in[i];
    }
    float* out = (float*)d_out;

    cudaFuncSetAttribute(k_gemm, cudaFuncAttributeMaxDynamicSharedMemorySize, SMEM_GEMM);

    k_minmax_part<<<dim3(8, 64), 256>>>(w);
    k_minmax_fin<<<1, 64>>>();
    k_build<<<dim3(64, 64), 256>>>(w);
    k_xprep_imean<<<dim3(8, 1024), 128>>>(x);
    k_gemm<<<GRID_P, 512, SMEM_GEMM>>>();
    k_combine<<<dim3(8, 1024), 512>>>(bias, out);
}

// round 17
// speedup vs baseline: 1.4595x; 1.1287x over previous
#include <cuda_runtime.h>
#include <cuda_fp16.h>
#include <cstdint>

// ---------------- problem constants ----------------
#define TSZ   512
#define NTILE 64
#define ITN   8

#define GMIN   1e-6f
#define GDIFF  ((float)(1.0e-4 - 1.0e-6))
#define STEPQ  ((float)((1.0e-4 - 1.0e-6) / 15.0))
#define RSTEPQ ((float)(15.0 / (1.0e-4 - 1.0e-6)))
#define FINF   3.402823466e38f
#define GSCALE 8192.0f
#define GINV   (1.0f / 8192.0f)

typedef unsigned int uint32;
typedef unsigned long long ull;

// ---------------- scratch (static device memory) ----------------
__device__ __half g_x16[(size_t)1024 * 4096];
__device__ __half g_Gh[(size_t)NTILE * TSZ * TSZ];   // geff*8192 hi, [t][n][k]
__device__ __half g_Gl[(size_t)NTILE * TSZ * TSZ];   // geff*8192 lo
__device__ __half g_Qi[(size_t)NTILE * TSZ * TSZ];   // quant code 0..15
__device__ float g_cur [(size_t)NTILE * 1024 * TSZ];  // currents, fp32 (precision-critical)
__device__ float g_part[(size_t)NTILE * 4 * 1024 * 6];
__device__ float g_s[NTILE], g_wmin[NTILE];
__device__ float g_pmin[NTILE * 8], g_pmax[NTILE * 8];
__device__ float g_xsum[1024 * ITN];                  // sums of x~ (fp16-rounded x)
__device__ float g_qsum[NTILE * TSZ];                 // per (t,k) colsum of q (exact int)
__device__ float g_idot[(size_t)1024 * ITN * 8];      // x~ . qsum per (b,it,ot)

// ---------------- PTX helpers ----------------
__device__ __forceinline__ uint32 smem_u32(const void* p) {
    uint32 a;
    asm("{ .reg .u64 t; cvta.to.shared.u64 t, %1; cvt.u32.u64 %0, t; }" : "=r"(a) : "l"(p));
    return a;
}
__device__ __forceinline__ void cpa16(uint32 dst, const void* src) {
    asm volatile("cp.async.cg.shared.global [%0], [%1], 16;" :: "r"(dst), "l"(src));
}
__device__ __forceinline__ void ldm_x4(uint32* r, uint32 addr) {
    asm volatile("ldmatrix.sync.aligned.m8n8.x4.shared.b16 {%0,%1,%2,%3}, [%4];"
                 : "=r"(r[0]), "=r"(r[1]), "=r"(r[2]), "=r"(r[3]) : "r"(addr));
}
__device__ __forceinline__ void mma16816(float* c, const uint32* a, const uint32* b) {
    asm volatile(
        "mma.sync.aligned.m16n8k16.row.col.f32.f16.f16.f32 "
        "{%0,%1,%2,%3}, {%4,%5,%6,%7}, {%8,%9}, {%0,%1,%2,%3};"
        : "+f"(c[0]), "+f"(c[1]), "+f"(c[2]), "+f"(c[3])
        : "r"(a[0]), "r"(a[1]), "r"(a[2]), "r"(a[3]), "r"(b[0]), "r"(b[1]));
}

// ---------------- kernel 1a: per-tile min/max partials + qsum zeroing ----------------
__global__ void k_minmax_part(const float* __restrict__ w) {
    int t = blockIdx.y, chunk = blockIdx.x;
    int it = t >> 3, ot = t & 7;
    int tid = threadIdx.x;
    if (tid < 64) g_qsum[t * 512 + chunk * 64 + tid] = 0.0f;
    float mn0 = FINF, mn1 = FINF, mn2 = FINF, mn3 = FINF;
    float mx0 = -FINF, mx1 = -FINF, mx2 = -FINF, mx3 = -FINF;
    #pragma unroll 8
    for (int k = 0; k < 32; k++) {
        int e = (chunk * 8192 + k * 256 + tid) * 4;
        int i = e >> 9, j = e & 511;
        float4 v = *(const float4*)&w[(size_t)(it * TSZ + i) * 4096 + ot * TSZ + j];
        mn0 = fminf(mn0, v.x); mx0 = fmaxf(mx0, v.x);
        mn1 = fminf(mn1, v.y); mx1 = fmaxf(mx1, v.y);
        mn2 = fminf(mn2, v.z); mx2 = fmaxf(mx2, v.z);
        mn3 = fminf(mn3, v.w); mx3 = fmaxf(mx3, v.w);
    }
    float mn = fminf(fminf(mn0, mn1), fminf(mn2, mn3));
    float mx = fmaxf(fmaxf(mx0, mx1), fmaxf(mx2, mx3));
    #pragma unroll
    for (int o = 16; o > 0; o >>= 1) {
        mn = fminf(mn, __shfl_xor_sync(0xffffffffu, mn, o));
        mx = fmaxf(mx, __shfl_xor_sync(0xffffffffu, mx, o));
    }
    __shared__ float smn[8], smx[8];
    if ((tid & 31) == 0) { smn[tid >> 5] = mn; smx[tid >> 5] = mx; }
    __syncthreads();
    if (tid == 0) {
        float a = smn[0], b = smx[0];
        #pragma unroll
        for (int q = 1; q < 8; q++) { a = fminf(a, smn[q]); b = fmaxf(b, smx[q]); }
        g_pmin[t * 8 + chunk] = a; g_pmax[t * 8 + chunk] = b;
    }
}

// ---------------- kernel 2: build Gh/Gl/Qi; s/wmin derived in-block (fin folded) ----------------
__global__ void __launch_bounds__(256) k_build(const float* __restrict__ w) {
    __shared__ __half sGh[64][72], sGl[64][72], sQi[64][72];
    __shared__ float s_sc[2];
    int sub = blockIdx.x, t = blockIdx.y;
    int it = t >> 3, ot = t & 7;
    int ib = sub >> 3, jb = sub & 7;
    int i0 = ib * 64, j0 = jb * 64;
    int tid = threadIdx.x;

    if (tid == 0) {
        float mn = g_pmin[t * 8], mx = g_pmax[t * 8];
        #pragma unroll
        for (int c = 1; c < 8; c++) {
            mn = fminf(mn, g_pmin[t * 8 + c]);
            mx = fmaxf(mx, g_pmax[t * 8 + c]);
        }
        float denom = __fadd_rn(__fsub_rn(mx, mn), 1e-12f);
        float sv = __fdiv_rn(GDIFF, denom);
        s_sc[0] = sv; s_sc[1] = mn;
        if (sub == 0) { g_s[t] = sv; g_wmin[t] = mn; }
    }
    __syncthreads();
    float s = s_sc[0], wmin = s_sc[1];

    int j = tid & 63;          // n within subtile
    int i8b = tid >> 6;        // 0..3 (k-octet), iter adds 4

    #pragma unroll
    for (int iter = 0; iter < 2; iter++) {
        int i8 = i8b + iter * 4;             // 0..7
        __align__(16) __half hGh[8], hGl[8], hQi[8];
        #pragma unroll
        for (int l = 0; l < 8; l++) {
            int i = i8 * 8 + l;              // k within subtile
            float v = w[(size_t)(it * TSZ + i0 + i) * 4096 + ot * TSZ + j0 + j];
            float t1   = __fsub_rn(v, wmin);
            float t2   = __fmul_rn(t1, s);
            float cond = __fadd_rn(t2, GMIN);
            float u    = __fsub_rn(cond, GMIN);
            float vv   = __fmul_rn(u, RSTEPQ);
            float q    = rintf(vv);
            float cq   = __fadd_rn(__fmul_rn(q, STEPQ), GMIN);
            float inv  = __fdividef(1.0f, cq);
            float rw   = (float)(2 * (513 + (j0 + j) - (i0 + i)));
            float ge   = __fdividef(1.0f, inv + rw);
            float gs   = ge * GSCALE;
            __half gh  = __float2half_rn(gs);
            hGh[l] = gh;
            hGl[l] = __float2half_rn(__fsub_rn(gs, __half2float(gh)));
            hQi[l] = __float2half_rn(q);
        }
        *(uint4*)&sGh[j][i8 * 8] = *(const uint4*)hGh;
        *(uint4*)&sGl[j][i8 * 8] = *(const uint4*)hGl;
        *(uint4*)&sQi[j][i8 * 8] = *(const uint4*)hQi;
    }
    __syncthreads();

    size_t obase = (size_t)t * 262144 + (size_t)j0 * 512 + i0;
    #pragma unroll
    for (int iter = 0; iter < 2; iter++) {
        int L = iter * 256 + tid;
        int n = L >> 3, k8 = (L & 7) * 8;
        size_t o = obase + (size_t)n * 512 + k8;
        *(uint4*)&g_Gh[o] = *(const uint4*)&sGh[n][k8];
        *(uint4*)&g_Gl[o] = *(const uint4*)&sGl[n][k8];
        *(uint4*)&g_Qi[o] = *(const uint4*)&sQi[n][k8];
    }

    if (tid < 64) {
        float sum = 0.0f;
        #pragma unroll
        for (int jj = 0; jj < 64; jj++) sum += __half2float(sQi[jj][tid]);
        atomicAdd(&g_qsum[t * 512 + i0 + tid], sum);
    }
}

// ---------------- kernel 3: fused x->fp16 + xsum~ + idot (runs AFTER k_build) ----------------
__global__ void __launch_bounds__(128) k_xprep_imean(const float* __restrict__ x) {
    int it = blockIdx.x, b = blockIdx.y, tid = threadIdx.x;
    size_t base = (size_t)b * 4096 + it * TSZ + tid * 4;
    float4 v = *(const float4*)&x[base];
    __half h[4] = { __float2half_rn(v.x), __float2half_rn(v.y),
                    __float2half_rn(v.z), __float2half_rn(v.w) };
    *(ull*)&g_x16[base] = *(const ull*)h;
    float x0 = __half2float(h[0]), x1 = __half2float(h[1]);
    float x2 = __half2float(h[2]), x3 = __half2float(h[3]);
    float s = x0 + x1 + x2 + x3;
    float acc[8];
    #pragma unroll
    for (int ot = 0; ot < 8; ot++) {
        const float4 qv = *(const float4*)&g_qsum[(it * 8 + ot) * 512 + tid * 4];
        acc[ot] = x0 * qv.x + x1 * qv.y + x2 * qv.z + x3 * qv.w;
    }
    __shared__ float sm[4][9];
    #pragma unroll
    for (int o = 16; o > 0; o >>= 1) s += __shfl_down_sync(0xffffffffu, s, o);
    if ((tid & 31) == 0) sm[tid >> 5][8] = s;
    #pragma unroll
    for (int ot = 0; ot < 8; ot++) {
        float a = acc[ot];
        #pragma unroll
        for (int o = 16; o > 0; o >>= 1) a += __shfl_down_sync(0xffffffffu, a, o);
        if ((tid & 31) == 0) sm[tid >> 5][ot] = a;
    }
    __syncthreads();
    if (tid < 8)
        g_idot[((size_t)b * ITN + it) * 8 + tid] =
            sm[0][tid] + sm[1][tid] + sm[2][tid] + sm[3][tid];
    if (tid == 8)
        g_xsum[b * ITN + it] = sm[0][8] + sm[1][8] + sm[2][8] + sm[3][8];
}

// ---------------- kernel 4: PERSISTENT GEMM, 512 threads (4 warps/SMSP) ----------------
#define PITCH 144
#define ASZ   18432
#define OFF_X  0
#define OFF_GH (1 * ASZ)
#define OFF_GL (2 * ASZ)
#define OFF_QI (3 * ASZ)
#define STAGE  (4 * ASZ)
#define NSTAGE 3
#define STATS_BYTES (128 * 4 * 5 * 4)
#define SMEM_GEMM (NSTAGE * STAGE + STATS_BYTES)
#define NITEMS 2048
#define GRID_P 148

__global__ void __launch_bounds__(512, 1) k_gemm() {
    extern __shared__ char smem[];
    uint32 sb = smem_u32(smem);
    float* stats = (float*)(smem + NSTAGE * STAGE);
    int tid = threadIdx.x;

    int lane = tid & 31, wid = tid >> 5;          // 16 warps
    int wm0 = (wid >> 2) * 32;
    int wn0 = (wid & 3) * 32;
    int wnid = wid & 3;
    int a_row = lane & 15;
    int a_koff = ((lane >> 4) & 1) * 16;
    int b_row = ((lane >> 4) & 1) * 8 + (lane & 7);
    int b_koff = ((lane >> 3) & 1) * 16;
    int grp = lane >> 2, qd = lane & 3;

    int bid = blockIdx.x;
    int nit = (NITEMS - bid + GRID_P - 1) / GRID_P;
    if (nit <= 0) return;
    int last_s = nit * 8 - 1;

    auto issue_seq = [&](int s) {
        int item = bid + (s >> 3) * GRID_P;
        int kk = (s & 7) * 64;
        int nb = item & 3, mb = (item >> 2) & 7, t = item >> 5;
        const __half* Ax = g_x16 + (size_t)(mb * 128) * 4096 + (t >> 3) * 512;
        size_t bbase = (size_t)t * 262144 + (size_t)(nb * 128) * 512;
        const __half* Bh = g_Gh + bbase;
        const __half* Bl = g_Gl + bbase;
        const __half* Bq = g_Qi + bbase;
        uint32 sbuf = sb + (uint32)(s % NSTAGE) * STAGE;
        #pragma unroll
        for (int L0 = 0; L0 < 2; L0++) {
            int L = L0 * 512 + tid;            // 0..1023
            int r = L >> 3, ch = L & 7;        // row, 16B chunk
            uint32 d = sbuf + r * PITCH + ch * 16;
            int soA = r * 4096 + kk + ch * 8;
            int soB = r * 512  + kk + ch * 8;
            cpa16(d + OFF_X,  Ax + soA);
            cpa16(d + OFF_GH, Bh + soB);
            cpa16(d + OFF_GL, Bl + soB);
            cpa16(d + OFF_QI, Bq + soB);
        }
        asm volatile("cp.async.commit_group;");
    };

    issue_seq(0);
    if (last_s >= 1) issue_seq(1);

    for (int ii = 0; ii < nit; ii++) {
        int item = bid + ii * GRID_P;

        float acc_c[2][4][4];
        float acc_i[2][4][4];
        #pragma unroll
        for (int i = 0; i < 2; i++)
            #pragma unroll
            for (int j = 0; j < 4; j++)
                #pragma unroll
                for (int r = 0; r < 4; r++) { acc_c[i][j][r] = 0.f; acc_i[i][j][r] = 0.f; }

        for (int c = 0; c < 8; c++) {
            int s = ii * 8 + c;
            if (s + 1 <= last_s) asm volatile("cp.async.wait_group 1;" ::: "memory");
            else                 asm volatile("cp.async.wait_group 0;" ::: "memory");
            __syncthreads();
            if (s + 2 <= last_s) issue_seq(s + 2);

            uint32 sbuf = sb + (uint32)(s % NSTAGE) * STAGE;
            #pragma unroll
            for (int ks = 0; ks < 4; ks++) {
                uint32 kb = ks * 32;
                uint32 ax[2][4];
                #pragma unroll
                for (int i = 0; i < 2; i++) {
                    uint32 ad = sbuf + (uint32)(wm0 + i * 16 + a_row) * PITCH + kb + a_koff;
                    ldm_x4(ax[i], ad + OFF_X);
                }
                uint32 gh[4][2], gl[4][2], qi[4][2];
                #pragma unroll
                for (int j2 = 0; j2 < 2; j2++) {
                    uint32 bd = sbuf + (uint32)(wn0 + j2 * 16 + b_row) * PITCH + kb + b_koff;
                    uint32 r4[4];
                    ldm_x4(r4, bd + OFF_GH);
                    gh[2*j2][0] = r4[0]; gh[2*j2][1] = r4[1];
                    gh[2*j2+1][0] = r4[2]; gh[2*j2+1][1] = r4[3];
                    ldm_x4(r4, bd + OFF_GL);
                    gl[2*j2][0] = r4[0]; gl[2*j2][1] = r4[1];
                    gl[2*j2+1][0] = r4[2]; gl[2*j2+1][1] = r4[3];
                    ldm_x4(r4, bd + OFF_QI);
                    qi[2*j2][0] = r4[0]; qi[2*j2][1] = r4[1];
                    qi[2*j2+1][0] = r4[2]; qi[2*j2+1][1] = r4[3];
                }
                #pragma unroll
                for (int i = 0; i < 2; i++) {
                    #pragma unroll
                    for (int j = 0; j < 4; j++) mma16816(acc_c[i][j], ax[i], gh[j]);
                    #pragma unroll
                    for (int j = 0; j < 4; j++) mma16816(acc_i[i][j], ax[i], qi[j]);
                    #pragma unroll
                    for (int j = 0; j < 4; j++) mma16816(acc_c[i][j], ax[i], gl[j]);
                }
            }
        }

        // ---- epilogue: rescale currents (GINV), store fp32, stats in FINAL units ----
        int nb = item & 3, mb = (item >> 2) & 7, t = item >> 5;
        size_t rowbase = (size_t)t * 1024 + (size_t)mb * 128;
        #pragma unroll
        for (int i = 0; i < 2; i++)
            #pragma unroll
            for (int j = 0; j < 4; j++)
                #pragma unroll
                for (int r = 0; r < 4; r++) acc_c[i][j][r] *= GINV;

        #pragma unroll
        for (int i = 0; i < 2; i++)
            #pragma unroll
            for (int h = 0; h < 2; h++) {
                int r = wm0 + i * 16 + h * 8 + grp;
                size_t gbb = (rowbase + r) * 512 + nb * 128 + wn0 + qd * 2;
                #pragma unroll
                for (int j = 0; j < 4; j++)
                    *(float2*)&g_cur[gbb + j * 8] =
                        make_float2(acc_c[i][j][2*h], acc_c[i][j][2*h+1]);
            }

        #pragma unroll
        for (int i = 0; i < 2; i++)
            #pragma unroll
            for (int h = 0; h < 2; h++) {
                float cs = 0.f, cmx = -FINF, cmn = FINF;
                float imx = -FINF, imn = FINF;
                #pragma unroll
                for (int j = 0; j < 4; j++) {
                    float v0 = acc_c[i][j][2*h], v1 = acc_c[i][j][2*h+1];
                    cs += v0 + v1; cmx = fmaxf(cmx, fmaxf(v0, v1)); cmn = fminf(cmn, fminf(v0, v1));
                    float u0 = acc_i[i][j][2*h], u1 = acc_i[i][j][2*h+1];
                    imx = fmaxf(imx, fmaxf(u0, u1)); imn = fminf(imn, fminf(u0, u1));
                }
                #pragma unroll
                for (int o = 1; o <= 2; o <<= 1) {
                    cs  += __shfl_xor_sync(0xffffffffu, cs, o);
                    cmx  = fmaxf(cmx, __shfl_xor_sync(0xffffffffu, cmx, o));
                    cmn  = fminf(cmn, __shfl_xor_sync(0xffffffffu, cmn, o));
                    imx  = fmaxf(imx, __shfl_xor_sync(0xffffffffu, imx, o));
                    imn  = fminf(imn, __shfl_xor_sync(0xffffffffu, imn, o));
                }
                if (qd == 0) {
                    int r = wm0 + i * 16 + h * 8 + grp;
                    float* p = &stats[(r * 4 + wnid) * 5];
                    p[0] = cs; p[1] = cmx; p[2] = cmn; p[3] = imx; p[4] = imn;
                }
            }
        __syncthreads();
        if (tid < 128) {
            float cs = 0.f, cmx = -FINF, cmn = FINF;
            float imx = -FINF, imn = FINF;
            #pragma unroll
            for (int wn = 0; wn < 4; wn++) {
                const float* p = &stats[(tid * 4 + wn) * 5];
                cs += p[0]; cmx = fmaxf(cmx, p[1]); cmn = fminf(cmn, p[2]);
                imx = fmaxf(imx, p[3]); imn = fminf(imn, p[4]);
            }
            float* p = &g_part[(((size_t)t * 4 + nb) * 1024 + (mb * 128 + tid)) * 6];
            p[0] = cs; p[1] = cmx; p[2] = cmn; p[3] = imx; p[4] = imn;
        }
        __syncthreads();   // stats smem reused next item
    }
}

// ---------------- kernel 5: combine (block-level stats staging in smem) ----------------
__global__ void __launch_bounds__(512) k_combine(const float* __restrict__ bias,
                                                 float* __restrict__ out) {
    int ot = blockIdx.x, b = blockIdx.y, j = threadIdx.x;
    __shared__ float sred[8][9];  // [it]: cs,cmx,cmn,amx,amn,xs,idot,s,wmin
    if (j < 8) {
        int it = j;
        int t = it * 8 + ot;
        float cs = 0.f, cmx = -FINF, cmn = FINF, amx = -FINF, amn = FINF;
        #pragma unroll
        for (int nb = 0; nb < 4; nb++) {   // identical order to previous per-thread loop
            const float* p = &g_part[(((size_t)t * 4 + nb) * 1024 + b) * 6];
            cs += p[0]; cmx = fmaxf(cmx, p[1]); cmn = fminf(cmn, p[2]);
            amx = fmaxf(amx, p[3]); amn = fminf(amn, p[4]);
        }
        sred[it][0] = cs;  sred[it][1] = cmx; sred[it][2] = cmn;
        sred[it][3] = amx; sred[it][4] = amn;
        sred[it][5] = g_xsum[b * ITN + it];
        sred[it][6] = g_idot[((size_t)b * ITN + it) * 8 + ot];
        sred[it][7] = g_s[t];
        sred[it][8] = g_wmin[t];
    }
    __syncthreads();

    float acc = 0.0f;
    #pragma unroll
    for (int it = 0; it < ITN; it++) {
        int t = it * 8 + ot;
        float cur = g_cur[((size_t)t * 1024 + b) * 512 + j];
        float cs  = sred[it][0], cmx = sred[it][1], cmn = sred[it][2];
        float amx = sred[it][3], amn = sred[it][4];
        float xs  = sred[it][5], idot = sred[it][6];
        float s   = sred[it][7], wmin = sred[it][8];
        float cmean = cs * (1.0f / 512.0f);
        float imean = __fadd_rn(__fmul_rn(STEPQ, idot * (1.0f / 512.0f)),
                                __fmul_rn(GMIN, xs));
        float coeff = __fdiv_rn(__fmul_rn(STEPQ, __fsub_rn(amx, amn)),
                                __fadd_rn(__fsub_rn(cmx, cmn), 1e-8f));
        float off = __fmul_rn(xs, __fsub_rn(GMIN, __fmul_rn(s, wmin)));
        float val = __fadd_rn(__fmul_rn(__fsub_rn(cur, cmean), coeff), imean);
        acc += __fdiv_rn(__fsub_rn(val, off), s);
    }
    out[(size_t)b * 4096 + ot * TSZ + j] = __fadd_rn(acc, bias[ot * TSZ + j]);
}

// ---------------- launch ----------------
extern "C" void kernel_launch(void* const* d_in, const int* in_sizes, int n_in,
                              void* d_out, int out_size) {
    const float* x = nullptr; const float* w = nullptr; const float* bias = nullptr;
    for (int i = 0; i < n_in; i++) {
        if (in_sizes[i] == 1024 * 4096)      x    = (const float*)d_in[i];
        else if (in_sizes[i] == 4096 * 4096) w    = (const float*)d_in[i];
        else if (in_sizes[i] == 4096)        bias = (const float*)d_in[i];
    }
    float* out = (float*)d_out;

    cudaFuncSetAttribute(k_gemm, cudaFuncAttributeMaxDynamicSharedMemorySize, SMEM_GEMM);

    k_minmax_part<<<dim3(8, 64), 256>>>(w);
    k_build<<<dim3(64, 64), 256>>>(w);
    k_xprep_imean<<<dim3(8, 1024), 128>>>(x);
    k_gemm<<<GRID_P, 512, SMEM_GEMM>>>();
    k_combine<<<dim3(8, 1024), 512>>>(bias, out);
}